// round 9
// baseline (speedup 1.0000x reference)
#include <cuda_runtime.h>
#include <cuda_fp16.h>
#include <cstdint>
#include <math.h>

#define B_   16
#define S_   2048
#define E_   256
#define L_   2
#define NQ_  8
#define FFN_ 512
#define C_   2
#define M_   (B_*S_)   // 32768 rows

// ---------------- scratch (__device__ globals; no allocations) ---------------
__device__ float g_x[(size_t)M_*E_];                      // 32 MB
__device__ __align__(128) __half g_ahi[(size_t)M_*E_];    // 16 MB  attn A hi
__device__ __align__(128) __half g_alo[(size_t)M_*E_];    // 16 MB  attn A lo
__device__ __align__(128) __half g_hhi[(size_t)M_*FFN_];  // 32 MB  ffn h hi
__device__ __align__(128) __half g_hlo[(size_t)M_*FFN_];  // 32 MB  ffn h lo
__device__ __align__(128) __half g_wh[4*256*512];         // Wt[n][k] fp16
__device__ float g_pp[512*E_];                            // pool partials

// ---------------- PTX helpers ------------------------------------------------
__device__ __forceinline__ uint32_t s2u(const void* p) {
    uint32_t a;
    asm("{ .reg .u64 t; cvta.to.shared.u64 t, %1; cvt.u32.u64 %0, t; }"
        : "=r"(a) : "l"(p));
    return a;
}
__device__ __forceinline__ void cp16(uint32_t dst, const void* src) {
    asm volatile("cp.async.cg.shared.global [%0], [%1], 16;" :: "r"(dst), "l"(src));
}
__device__ __forceinline__ void cp_commit() {
    asm volatile("cp.async.commit_group;" ::: "memory");
}
__device__ __forceinline__ void cp_wait1() {
    asm volatile("cp.async.wait_group 1;" ::: "memory");
}
__device__ __forceinline__ void cp_wait0() {
    asm volatile("cp.async.wait_group 0;" ::: "memory");
}
__device__ __forceinline__ void ldm_x4(uint32_t& r0, uint32_t& r1, uint32_t& r2,
                                       uint32_t& r3, uint32_t addr) {
    asm volatile("ldmatrix.sync.aligned.m8n8.x4.shared.b16 {%0,%1,%2,%3}, [%4];"
                 : "=r"(r0), "=r"(r1), "=r"(r2), "=r"(r3) : "r"(addr));
}
__device__ __forceinline__ void mma16816(float* c, uint32_t a0, uint32_t a1,
                                         uint32_t a2, uint32_t a3,
                                         uint32_t b0, uint32_t b1) {
    asm volatile(
        "mma.sync.aligned.m16n8k16.row.col.f32.f16.f16.f32 "
        "{%0,%1,%2,%3}, {%4,%5,%6,%7}, {%8,%9}, {%0,%1,%2,%3};"
        : "+f"(c[0]), "+f"(c[1]), "+f"(c[2]), "+f"(c[3])
        : "r"(a0), "r"(a1), "r"(a2), "r"(a3), "r"(b0), "r"(b1));
}

// ---------------- embed + PE + fused prep for layer-0 attn -------------------
__global__ void k_embed(const int* __restrict__ tok, const float* __restrict__ emb,
                        const float* __restrict__ th) {
    int row = blockIdx.x;
    int e   = threadIdx.x;
    int t   = tok[row];
    int s   = row & (S_ - 1);
    int i   = e >> 1;
    float freq = expf(-(float)(2 * i) * (9.210340371976184f / (float)E_));
    float ang  = (float)s * freq;
    float pe   = (e & 1) ? cosf(ang) : sinf(ang);
    size_t idx = (size_t)row * E_ + e;
    float x = emb[(size_t)t * E_ + e] + pe;
    g_x[idx] = x;
    float a = cosf(x + th[e & 63]);
    __half hi = __float2half_rn(a);
    g_ahi[idx] = hi;
    g_alo[idx] = __float2half_rn(a - __half2float(hi));
}

// ---------------- weight convert + transpose (fp16) --------------------------
__global__ void k_convw(const float* __restrict__ cw, const float* __restrict__ l2w) {
    int slot = blockIdx.y;
    int n    = blockIdx.x;
    int K    = (slot < 2) ? 256 : 512;
    const float* src = (slot < 2) ? (cw + (size_t)slot * E_ * E_)
                                  : (l2w + (size_t)(slot - 2) * FFN_ * E_);
    for (int k = threadIdx.x; k < K; k += 256) {
        float w = src[(size_t)k * E_ + n];
        g_wh[(size_t)slot * 131072 + (size_t)n * K + k] = __float2half_rn(w);
    }
}

// ---------------- fused GEMM (2-term fp16, BK=64) + LN + producers -----------
// BM=64, BN=256, BK=64 (128B rows, XOR-8 swizzle), 256 threads (2Mx4N warps).
// 2-stage double buffer, 2 CTAs/SM.
// MODE 0: attn GEMM -> LN1 -> g_x + compute full ffn1 h -> g_hhi/g_hlo
// MODE 1: ffn GEMM  -> LN2 -> g_x + cos(x+thetaNext) hi/lo -> g_ahi/g_alo
// MODE 2: ffn GEMM  -> LN2 -> pool partials only
#define A_HI_O  0
#define A_LO_O  8192
#define W_O     16384
#define STAGE   49152
#define SME     (2*STAGE)            // 98304 -> 2 CTAs/SM
// epilogue smem layout (reuses stage memory after mainloop):
#define RED_O   0                    // [64][4] float2   2048
#define MR_O    2048                 // [64] float2       512
#define QSH_O   4096                 // [64][8] float    2048  (MODE 0)
#define PPS_O   4096                 // [2][256] float   2048  (MODE 2)
#define W1S_O   8192                 // [512][9] float  18432  (MODE 0)
#define B1S_O   26624                // [512] float      2048  (MODE 0)

template <int K, int MODE>
__global__ void __launch_bounds__(256, 2)
k_gf(const __half* __restrict__ Agh, const __half* __restrict__ Agl,
     const __half* __restrict__ Whi,
     const float* __restrict__ bias,
     const float* __restrict__ lnG, const float* __restrict__ lnB,
     const float* __restrict__ thN,                       // MODE 1
     const float* __restrict__ fTh,                       // MODE 0
     const float* __restrict__ W1, const float* __restrict__ b1) {   // MODE 0
    constexpr int CH = K >> 6;
    extern __shared__ __align__(16) char smem[];
    uint32_t sb = s2u(smem);
    int tid = threadIdx.x, lane = tid & 31, wid = tid >> 5;
    int wm = wid >> 2, wn = wid & 3;
    size_t bm = (size_t)blockIdx.x * 64;

    float acc[2][8][4];
#pragma unroll
    for (int i = 0; i < 2; i++)
#pragma unroll
        for (int j = 0; j < 8; j++)
#pragma unroll
            for (int c = 0; c < 4; c++) acc[i][j][c] = 0.f;

    int part = tid & 7, rbase = tid >> 3;                  // rbase 0..31
    uint32_t swc = (uint32_t)(part ^ (rbase & 7)) << 4;

    auto load_stage = [&](int st, int ch) {
        uint32_t dst = sb + st * STAGE;
        int kk = ch << 6;
#pragma unroll
        for (int i = 0; i < 2; i++) {
            int r = rbase + i * 32;
            cp16(dst + A_HI_O + r * 128 + swc,
                 Agh + (bm + r) * (size_t)K + kk + part * 8);
            cp16(dst + A_LO_O + r * 128 + swc,
                 Agl + (bm + r) * (size_t)K + kk + part * 8);
        }
#pragma unroll
        for (int i = 0; i < 8; i++) {
            int r = rbase + i * 32;
            cp16(dst + W_O + r * 128 + swc, Whi + (size_t)r * K + kk + part * 8);
        }
        cp_commit();
    };

    load_stage(0, 0);
    load_stage(1, 1);

    uint32_t rowA = wm * 32 + (lane & 15);
    uint32_t rxA  = rowA & 7;
    uint32_t cA   = (uint32_t)lane >> 4;                   // 0..1
    uint32_t rowB = wn * 64 + ((lane >> 4) & 1) * 8 + (lane & 7);
    uint32_t rxB  = (uint32_t)lane & 7;
    uint32_t cB   = ((uint32_t)lane >> 3) & 1;

    for (int cc = 0; cc < CH; cc++) {
        if (cc + 1 < CH) cp_wait1(); else cp_wait0();
        __syncthreads();
        uint32_t stg = sb + (cc & 1) * STAGE;
        uint32_t aB  = stg + A_HI_O + rowA * 128;
        uint32_t bB  = stg + W_O + rowB * 128;

#pragma unroll
        for (int kb = 0; kb < 4; kb++) {
            uint32_t colA = (((uint32_t)(kb * 2) + cA) ^ rxA) << 4;
            uint32_t colB = (((uint32_t)(kb * 2) + cB) ^ rxB) << 4;
            uint32_t b[16];
#pragma unroll
            for (int n2 = 0; n2 < 4; n2++)
                ldm_x4(b[n2 * 4], b[n2 * 4 + 1], b[n2 * 4 + 2], b[n2 * 4 + 3],
                       bB + n2 * 2048 + colB);
            uint32_t h0[2], h1[2], h2[2], h3[2];
#pragma unroll
            for (int mi = 0; mi < 2; mi++)
                ldm_x4(h0[mi], h1[mi], h2[mi], h3[mi], aB + mi * 2048 + colA);
#pragma unroll
            for (int mi = 0; mi < 2; mi++)
#pragma unroll
                for (int n2 = 0; n2 < 4; n2++) {
                    mma16816(acc[mi][n2 * 2],     h0[mi], h1[mi], h2[mi], h3[mi],
                             b[n2 * 4],     b[n2 * 4 + 1]);
                    mma16816(acc[mi][n2 * 2 + 1], h0[mi], h1[mi], h2[mi], h3[mi],
                             b[n2 * 4 + 2], b[n2 * 4 + 3]);
                }
#pragma unroll
            for (int mi = 0; mi < 2; mi++)
                ldm_x4(h0[mi], h1[mi], h2[mi], h3[mi],
                       aB + (A_LO_O - A_HI_O) + mi * 2048 + colA);
#pragma unroll
            for (int mi = 0; mi < 2; mi++)
#pragma unroll
                for (int n2 = 0; n2 < 4; n2++) {
                    mma16816(acc[mi][n2 * 2],     h0[mi], h1[mi], h2[mi], h3[mi],
                             b[n2 * 4],     b[n2 * 4 + 1]);
                    mma16816(acc[mi][n2 * 2 + 1], h0[mi], h1[mi], h2[mi], h3[mi],
                             b[n2 * 4 + 2], b[n2 * 4 + 3]);
                }
        }
        __syncthreads();
        if (cc + 2 < CH) load_stage(cc & 1, cc + 2);
    }
    cp_wait0();
    __syncthreads();

    // ---------- epilogue: residual + LayerNorm (+ producers) ----------
    float2* red = (float2*)(smem + RED_O);
    float2* mr  = (float2*)(smem + MR_O);
    float*  qsh = (float*)(smem + QSH_O);
    float*  pps = (float*)(smem + PPS_O);
    float*  w1s = (float*)(smem + W1S_O);
    float*  b1s = (float*)(smem + B1S_O);

    if constexpr (MODE == 0) {
        // stage W1 (transposed to [f][n]) + b1; consumed after the mr sync
#pragma unroll
        for (int i = 0; i < 16; i++) {
            int idx = tid + i * 256;                    // 4096 total
            int n = idx >> 9, f = idx & 511;
            w1s[f * 9 + n] = W1[idx];
        }
        b1s[tid]       = b1[tid];
        b1s[tid + 256] = b1[tid + 256];
    }

    int mcol = wn * 64 + (lane & 3) * 2;
    int r0l  = wm * 32 + (lane >> 2);

#pragma unroll
    for (int mi = 0; mi < 2; mi++) {
        float s0 = 0, q0 = 0, s1 = 0, q1 = 0;
        size_t ra = bm + r0l + mi * 16;
#pragma unroll
        for (int ni = 0; ni < 8; ni++) {
            int col = mcol + ni * 8;
            float2 x0 = *(const float2*)(g_x + ra * E_ + col);
            float2 x1 = *(const float2*)(g_x + (ra + 8) * E_ + col);
            float bcx = bias[col], bcy = bias[col + 1];
            float v0 = acc[mi][ni][0] + bcx + x0.x;
            float v1 = acc[mi][ni][1] + bcy + x0.y;
            float v2 = acc[mi][ni][2] + bcx + x1.x;
            float v3 = acc[mi][ni][3] + bcy + x1.y;
            acc[mi][ni][0] = v0; acc[mi][ni][1] = v1;
            acc[mi][ni][2] = v2; acc[mi][ni][3] = v3;
            s0 += v0 + v1; q0 += v0 * v0 + v1 * v1;
            s1 += v2 + v3; q1 += v2 * v2 + v3 * v3;
        }
#pragma unroll
        for (int o = 1; o <= 2; o <<= 1) {
            s0 += __shfl_xor_sync(0xffffffffu, s0, o);
            q0 += __shfl_xor_sync(0xffffffffu, q0, o);
            s1 += __shfl_xor_sync(0xffffffffu, s1, o);
            q1 += __shfl_xor_sync(0xffffffffu, q1, o);
        }
        if ((lane & 3) == 0) {
            int rl = r0l + mi * 16;
            red[rl * 4 + wn] = make_float2(s0, q0);
            red[(rl + 8) * 4 + wn] = make_float2(s1, q1);
        }
    }
    __syncthreads();
    if (tid < 64) {
        float s = 0, q = 0;
#pragma unroll
        for (int j = 0; j < 4; j++) { float2 t = red[tid * 4 + j]; s += t.x; q += t.y; }
        float mean = s * (1.0f / E_);
        float var  = q * (1.0f / E_) - mean * mean;
        mr[tid] = make_float2(mean, rsqrtf(var + 1e-5f));
    }
    __syncthreads();

    float cf0 = 0.f, cf1 = 0.f;
    if constexpr (MODE == 0) {
        int c = (lane & 3) * 2;
        cf0 = cosf(fTh[c]); cf1 = cosf(fTh[c + 1]);
    }
    float ps[8][2];
    if constexpr (MODE == 2) {
#pragma unroll
        for (int ni = 0; ni < 8; ni++) { ps[ni][0] = 0.f; ps[ni][1] = 0.f; }
    }

#pragma unroll
    for (int mi = 0; mi < 2; mi++) {
        int rl = r0l + mi * 16;
        float2 m0 = mr[rl], m1 = mr[rl + 8];
        size_t ra = bm + rl;
#pragma unroll
        for (int ni = 0; ni < 8; ni++) {
            int col = mcol + ni * 8;
            float gx = lnG[col], gy = lnG[col + 1];
            float bx = lnB[col], by = lnB[col + 1];
            float o0 = (acc[mi][ni][0] - m0.x) * m0.y * gx + bx;
            float o1 = (acc[mi][ni][1] - m0.x) * m0.y * gy + by;
            float o2 = (acc[mi][ni][2] - m1.x) * m1.y * gx + bx;
            float o3 = (acc[mi][ni][3] - m1.x) * m1.y * gy + by;
            if constexpr (MODE != 2) {
                *(float2*)(g_x + ra * E_ + col) = make_float2(o0, o1);
                *(float2*)(g_x + (ra + 8) * E_ + col) = make_float2(o2, o3);
            }
            if constexpr (MODE == 0) {
                if (wn == 0 && ni == 0) {
                    int c = (lane & 3) * 2;
                    qsh[rl * 8 + c]           = cosf(o0) * cf0;
                    qsh[rl * 8 + c + 1]       = cosf(o1) * cf1;
                    qsh[(rl + 8) * 8 + c]     = cosf(o2) * cf0;
                    qsh[(rl + 8) * 8 + c + 1] = cosf(o3) * cf1;
                }
            }
            if constexpr (MODE == 1) {
                float t0 = thN[col & 63], t1 = thN[(col + 1) & 63];
                float a0 = cosf(o0 + t0), a1 = cosf(o1 + t1);
                float a2 = cosf(o2 + t0), a3 = cosf(o3 + t1);
                __half p0 = __float2half_rn(a0), p1 = __float2half_rn(a1);
                __half p2 = __float2half_rn(a2), p3 = __float2half_rn(a3);
                *(__half2*)(g_ahi + ra * E_ + col) = __halves2half2(p0, p1);
                *(__half2*)(g_ahi + (ra + 8) * E_ + col) = __halves2half2(p2, p3);
                *(__half2*)(g_alo + ra * E_ + col) =
                    __halves2half2(__float2half_rn(a0 - __half2float(p0)),
                                   __float2half_rn(a1 - __half2float(p1)));
                *(__half2*)(g_alo + (ra + 8) * E_ + col) =
                    __halves2half2(__float2half_rn(a2 - __half2float(p2)),
                                   __float2half_rn(a3 - __half2float(p3)));
            }
            if constexpr (MODE == 2) {
                ps[ni][0] += o0 + o2;
                ps[ni][1] += o1 + o3;
            }
        }
    }

    if constexpr (MODE == 0) {
        // ---- compute h = relu(q @ W1 + b1), split fp16, write g_hhi/g_hlo ----
        __syncthreads();                       // qsh / w1s / b1s ready
        int hrow = tid >> 2;                   // 0..63
        int cg   = tid & 3;
        float qr[8];
#pragma unroll
        for (int n = 0; n < 8; n++) qr[n] = qsh[hrow * 8 + n];
        size_t ra = bm + hrow;
#pragma unroll
        for (int jj = 0; jj < 16; jj++) {
            int f0 = cg * 8 + jj * 32;
            __half2 hp[4], lp[4];
#pragma unroll
            for (int v = 0; v < 4; v++) {
                int f = f0 + v * 2;
                float h0 = b1s[f], h1 = b1s[f + 1];
#pragma unroll
                for (int n = 0; n < 8; n++) {
                    h0 += qr[n] * w1s[f * 9 + n];
                    h1 += qr[n] * w1s[(f + 1) * 9 + n];
                }
                h0 = fmaxf(h0, 0.f); h1 = fmaxf(h1, 0.f);
                __half p0 = __float2half_rn(h0), p1 = __float2half_rn(h1);
                hp[v] = __halves2half2(p0, p1);
                lp[v] = __halves2half2(__float2half_rn(h0 - __half2float(p0)),
                                       __float2half_rn(h1 - __half2float(p1)));
            }
            *(uint4*)(g_hhi + ra * FFN_ + f0) = *(uint4*)hp;
            *(uint4*)(g_hlo + ra * FFN_ + f0) = *(uint4*)lp;
        }
    }

    if constexpr (MODE == 2) {
#pragma unroll
        for (int ni = 0; ni < 8; ni++)
#pragma unroll
            for (int o = 4; o <= 16; o <<= 1) {
                ps[ni][0] += __shfl_xor_sync(0xffffffffu, ps[ni][0], o);
                ps[ni][1] += __shfl_xor_sync(0xffffffffu, ps[ni][1], o);
            }
        if (lane < 4) {
#pragma unroll
            for (int ni = 0; ni < 8; ni++) {
                pps[wm * 256 + mcol + ni * 8]     = ps[ni][0];
                pps[wm * 256 + mcol + ni * 8 + 1] = ps[ni][1];
            }
        }
        __syncthreads();
        if (tid < 256) g_pp[blockIdx.x * 256 + tid] = pps[tid] + pps[256 + tid];
    }
}

// ---------------- classifier -------------------------------------------------
__global__ void k_cls(const float* __restrict__ w, const float* __restrict__ cb,
                      float* __restrict__ out) {
    __shared__ float sh[16];
    int b = blockIdx.x, e = threadIdx.x;
    float p = 0.f;
#pragma unroll 8
    for (int j = 0; j < 32; j++) p += g_pp[(b * 32 + j) * E_ + e];
    p *= (1.0f / (float)S_);
    float s0 = p * w[e * 2], s1 = p * w[e * 2 + 1];
    for (int o = 16; o > 0; o >>= 1) {
        s0 += __shfl_xor_sync(0xffffffffu, s0, o);
        s1 += __shfl_xor_sync(0xffffffffu, s1, o);
    }
    int wi = e >> 5;
    if ((e & 31) == 0) { sh[wi * 2] = s0; sh[wi * 2 + 1] = s1; }
    __syncthreads();
    if (e == 0) {
        float t0 = 0, t1 = 0;
#pragma unroll
        for (int j = 0; j < 8; j++) { t0 += sh[j * 2]; t1 += sh[j * 2 + 1]; }
        out[b * 2]     = t0 + cb[0];
        out[b * 2 + 1] = t1 + cb[1];
    }
}

// ---------------- host launcher ----------------------------------------------
extern "C" void kernel_launch(void* const* d_in, const int* in_sizes, int n_in,
                              void* d_out, int out_size) {
    const int*   tokens     = (const int*)d_in[0];
    const float* embed      = (const float*)d_in[1];
    const float* attn_theta = (const float*)d_in[2];
    const float* combine_w  = (const float*)d_in[3];
    const float* combine_b  = (const float*)d_in[4];
    const float* ffn_theta  = (const float*)d_in[5];
    const float* lin1_w     = (const float*)d_in[6];
    const float* lin1_b     = (const float*)d_in[7];
    const float* lin2_w     = (const float*)d_in[8];
    const float* lin2_b     = (const float*)d_in[9];
    const float* ln1_g      = (const float*)d_in[10];
    const float* ln1_b      = (const float*)d_in[11];
    const float* ln2_g      = (const float*)d_in[12];
    const float* ln2_b      = (const float*)d_in[13];
    const float* cls_w      = (const float*)d_in[14];
    const float* cls_b      = (const float*)d_in[15];
    float* out = (float*)d_out;

    __half *ahi, *alo, *hhi, *hlo, *wh;
    cudaGetSymbolAddress((void**)&ahi, g_ahi);
    cudaGetSymbolAddress((void**)&alo, g_alo);
    cudaGetSymbolAddress((void**)&hhi, g_hhi);
    cudaGetSymbolAddress((void**)&hlo, g_hlo);
    cudaGetSymbolAddress((void**)&wh,  g_wh);

    cudaFuncSetAttribute(k_gf<256, 0>, cudaFuncAttributeMaxDynamicSharedMemorySize, SME);
    cudaFuncSetAttribute(k_gf<512, 1>, cudaFuncAttributeMaxDynamicSharedMemorySize, SME);
    cudaFuncSetAttribute(k_gf<512, 2>, cudaFuncAttributeMaxDynamicSharedMemorySize, SME);

    k_embed<<<M_, 256>>>(tokens, embed, attn_theta);
    k_convw<<<dim3(256, 4), 256>>>(combine_w, lin2_w);

    // layer 0
    k_gf<256, 0><<<M_ / 64, 256, SME>>>(
        ahi, alo, wh + 0 * 131072, combine_b + 0 * E_,
        ln1_g + 0 * E_, ln1_b + 0 * E_, nullptr,
        ffn_theta + 0 * NQ_, lin1_w + 0 * NQ_ * FFN_, lin1_b + 0 * FFN_);
    k_gf<512, 1><<<M_ / 64, 256, SME>>>(
        hhi, hlo, wh + 2 * 131072, lin2_b + 0 * E_,
        ln2_g + 0 * E_, ln2_b + 0 * E_, attn_theta + 1 * 64,
        nullptr, nullptr, nullptr);
    // layer 1
    k_gf<256, 0><<<M_ / 64, 256, SME>>>(
        ahi, alo, wh + 1 * 131072, combine_b + 1 * E_,
        ln1_g + 1 * E_, ln1_b + 1 * E_, nullptr,
        ffn_theta + 1 * NQ_, lin1_w + 1 * NQ_ * FFN_, lin1_b + 1 * FFN_);
    k_gf<512, 2><<<M_ / 64, 256, SME>>>(
        hhi, hlo, wh + 3 * 131072, lin2_b + 1 * E_,
        ln2_g + 1 * E_, ln2_b + 1 * E_, nullptr,
        nullptr, nullptr, nullptr);

    k_cls<<<B_, 256>>>(cls_w, cls_b, out);
}

// round 10
// speedup vs baseline: 1.1346x; 1.1346x over previous
#include <cuda_runtime.h>
#include <cuda_fp16.h>
#include <cstdint>
#include <math.h>

#define B_   16
#define S_   2048
#define E_   256
#define L_   2
#define NQ_  8
#define FFN_ 512
#define C_   2
#define M_   (B_*S_)   // 32768 rows

// ---------------- scratch (__device__ globals; no allocations) ---------------
__device__ float g_x[(size_t)M_*E_];                      // 32 MB
__device__ __align__(128) __half g_ahi[(size_t)M_*E_];    // 16 MB  attn A hi
__device__ __align__(128) __half g_alo[(size_t)M_*E_];    // 16 MB  attn A lo
__device__ __align__(128) __half g_hh[(size_t)M_*FFN_];   // 32 MB  ffn h (fp16)
__device__ __align__(128) __half g_wh[4*256*512];         // Wt[n][k] fp16
__device__ float g_pp[512*E_];                            // pool partials

// ---------------- PTX helpers ------------------------------------------------
__device__ __forceinline__ uint32_t s2u(const void* p) {
    uint32_t a;
    asm("{ .reg .u64 t; cvta.to.shared.u64 t, %1; cvt.u32.u64 %0, t; }"
        : "=r"(a) : "l"(p));
    return a;
}
__device__ __forceinline__ void cp16(uint32_t dst, const void* src) {
    asm volatile("cp.async.cg.shared.global [%0], [%1], 16;" :: "r"(dst), "l"(src));
}
__device__ __forceinline__ void cp_commit() {
    asm volatile("cp.async.commit_group;" ::: "memory");
}
__device__ __forceinline__ void cp_wait1() {
    asm volatile("cp.async.wait_group 1;" ::: "memory");
}
__device__ __forceinline__ void cp_wait0() {
    asm volatile("cp.async.wait_group 0;" ::: "memory");
}
__device__ __forceinline__ void ldm_x4(uint32_t& r0, uint32_t& r1, uint32_t& r2,
                                       uint32_t& r3, uint32_t addr) {
    asm volatile("ldmatrix.sync.aligned.m8n8.x4.shared.b16 {%0,%1,%2,%3}, [%4];"
                 : "=r"(r0), "=r"(r1), "=r"(r2), "=r"(r3) : "r"(addr));
}
__device__ __forceinline__ void mma16816(float* c, uint32_t a0, uint32_t a1,
                                         uint32_t a2, uint32_t a3,
                                         uint32_t b0, uint32_t b1) {
    asm volatile(
        "mma.sync.aligned.m16n8k16.row.col.f32.f16.f16.f32 "
        "{%0,%1,%2,%3}, {%4,%5,%6,%7}, {%8,%9}, {%0,%1,%2,%3};"
        : "+f"(c[0]), "+f"(c[1]), "+f"(c[2]), "+f"(c[3])
        : "r"(a0), "r"(a1), "r"(a2), "r"(a3), "r"(b0), "r"(b1));
}

// ---------------- embed + PE + fused prep for layer-0 attn -------------------
__global__ void k_embed(const int* __restrict__ tok, const float* __restrict__ emb,
                        const float* __restrict__ th) {
    int row = blockIdx.x;
    int e   = threadIdx.x;
    int t   = tok[row];
    int s   = row & (S_ - 1);
    int i   = e >> 1;
    float freq = expf(-(float)(2 * i) * (9.210340371976184f / (float)E_));
    float ang  = (float)s * freq;
    float pe   = (e & 1) ? cosf(ang) : sinf(ang);
    size_t idx = (size_t)row * E_ + e;
    float x = emb[(size_t)t * E_ + e] + pe;
    g_x[idx] = x;
    float a = cosf(x + th[e & 63]);
    __half hi = __float2half_rn(a);
    g_ahi[idx] = hi;
    g_alo[idx] = __float2half_rn(a - __half2float(hi));
}

// ---------------- weight convert + transpose (fp16) --------------------------
__global__ void k_convw(const float* __restrict__ cw, const float* __restrict__ l2w) {
    int slot = blockIdx.y;
    int n    = blockIdx.x;
    int K    = (slot < 2) ? 256 : 512;
    const float* src = (slot < 2) ? (cw + (size_t)slot * E_ * E_)
                                  : (l2w + (size_t)(slot - 2) * FFN_ * E_);
    for (int k = threadIdx.x; k < K; k += 256) {
        float w = src[(size_t)k * E_ + n];
        g_wh[(size_t)slot * 131072 + (size_t)n * K + k] = __float2half_rn(w);
    }
}

// ---------------- fused GEMM + LN + producers --------------------------------
// BM=64, BN=256, BK=64 (128B rows, XOR-8 swizzle), 256 threads (2Mx4N warps).
// TERMS=2: D = Ah*W + Al*W (attn). TERMS=1: D = A*W (ffn, h single fp16).
// MODE 0: attn GEMM -> LN1 -> g_x + ffn1 h -> g_hh (fp16)
// MODE 1: ffn GEMM  -> LN2 -> g_x + cos(x+thetaNext) hi/lo
// MODE 2: ffn GEMM  -> LN2 -> pool partials only
// epilogue smem layout (reuses stage memory after mainloop):
#define RED_O   0                    // [64][4] float2   2048
#define MR_O    2048                 // [64] float2       512
#define QSH_O   4096                 // [64][8] float    2048  (MODE 0)
#define PPS_O   4096                 // [2][256] float   2048  (MODE 2)
#define W1S_O   8192                 // [512][9] float  18432  (MODE 0)
#define B1S_O   26624                // [512] float      2048  (MODE 0)
#define SME_ATT (2*(16384+32768))    // 98304
#define SME_FFN (2*(8192+32768))     // 81920

template <int K, int MODE, int TERMS>
__global__ void __launch_bounds__(256, 2)
k_gf(const __half* __restrict__ Agh, const __half* __restrict__ Agl,
     const __half* __restrict__ Whi,
     const float* __restrict__ bias,
     const float* __restrict__ lnG, const float* __restrict__ lnB,
     const float* __restrict__ thN,                       // MODE 1
     const float* __restrict__ fTh,                       // MODE 0
     const float* __restrict__ W1, const float* __restrict__ b1) {   // MODE 0
    constexpr int CH    = K >> 6;
    constexpr int A_LO_O = 8192;
    constexpr int W_O   = (TERMS == 2) ? 16384 : 8192;
    constexpr int STAGE = W_O + 32768;
    extern __shared__ __align__(16) char smem[];
    uint32_t sb = s2u(smem);
    int tid = threadIdx.x, lane = tid & 31, wid = tid >> 5;
    int wm = wid >> 2, wn = wid & 3;
    size_t bm = (size_t)blockIdx.x * 64;

    float acc[2][8][4];
#pragma unroll
    for (int i = 0; i < 2; i++)
#pragma unroll
        for (int j = 0; j < 8; j++)
#pragma unroll
            for (int c = 0; c < 4; c++) acc[i][j][c] = 0.f;

    int part = tid & 7, rbase = tid >> 3;                  // rbase 0..31
    uint32_t swc = (uint32_t)(part ^ (rbase & 7)) << 4;

    auto load_stage = [&](int st, int ch) {
        uint32_t dst = sb + st * STAGE;
        int kk = ch << 6;
#pragma unroll
        for (int i = 0; i < 2; i++) {
            int r = rbase + i * 32;
            cp16(dst + r * 128 + swc,
                 Agh + (bm + r) * (size_t)K + kk + part * 8);
            if constexpr (TERMS == 2)
                cp16(dst + A_LO_O + r * 128 + swc,
                     Agl + (bm + r) * (size_t)K + kk + part * 8);
        }
#pragma unroll
        for (int i = 0; i < 8; i++) {
            int r = rbase + i * 32;
            cp16(dst + W_O + r * 128 + swc, Whi + (size_t)r * K + kk + part * 8);
        }
        cp_commit();
    };

    load_stage(0, 0);
    load_stage(1, 1);

    uint32_t rowA = wm * 32 + (lane & 15);
    uint32_t rxA  = rowA & 7;
    uint32_t cA   = (uint32_t)lane >> 4;                   // 0..1
    uint32_t rowB = wn * 64 + ((lane >> 4) & 1) * 8 + (lane & 7);
    uint32_t rxB  = (uint32_t)lane & 7;
    uint32_t cB   = ((uint32_t)lane >> 3) & 1;

    for (int cc = 0; cc < CH; cc++) {
        if (cc + 1 < CH) cp_wait1(); else cp_wait0();
        __syncthreads();
        uint32_t stg = sb + (cc & 1) * STAGE;
        uint32_t aB  = stg + rowA * 128;
        uint32_t bB  = stg + W_O + rowB * 128;

#pragma unroll
        for (int kb = 0; kb < 4; kb++) {
            uint32_t colA = (((uint32_t)(kb * 2) + cA) ^ rxA) << 4;
            uint32_t colB = (((uint32_t)(kb * 2) + cB) ^ rxB) << 4;
            uint32_t b[16];
#pragma unroll
            for (int n2 = 0; n2 < 4; n2++)
                ldm_x4(b[n2 * 4], b[n2 * 4 + 1], b[n2 * 4 + 2], b[n2 * 4 + 3],
                       bB + n2 * 2048 + colB);
            uint32_t h0[2], h1[2], h2[2], h3[2];
#pragma unroll
            for (int mi = 0; mi < 2; mi++)
                ldm_x4(h0[mi], h1[mi], h2[mi], h3[mi], aB + mi * 2048 + colA);
#pragma unroll
            for (int mi = 0; mi < 2; mi++)
#pragma unroll
                for (int n2 = 0; n2 < 4; n2++) {
                    mma16816(acc[mi][n2 * 2],     h0[mi], h1[mi], h2[mi], h3[mi],
                             b[n2 * 4],     b[n2 * 4 + 1]);
                    mma16816(acc[mi][n2 * 2 + 1], h0[mi], h1[mi], h2[mi], h3[mi],
                             b[n2 * 4 + 2], b[n2 * 4 + 3]);
                }
            if constexpr (TERMS == 2) {
#pragma unroll
                for (int mi = 0; mi < 2; mi++)
                    ldm_x4(h0[mi], h1[mi], h2[mi], h3[mi],
                           aB + A_LO_O + mi * 2048 + colA);
#pragma unroll
                for (int mi = 0; mi < 2; mi++)
#pragma unroll
                    for (int n2 = 0; n2 < 4; n2++) {
                        mma16816(acc[mi][n2 * 2],     h0[mi], h1[mi], h2[mi], h3[mi],
                                 b[n2 * 4],     b[n2 * 4 + 1]);
                        mma16816(acc[mi][n2 * 2 + 1], h0[mi], h1[mi], h2[mi], h3[mi],
                                 b[n2 * 4 + 2], b[n2 * 4 + 3]);
                    }
            }
        }
        __syncthreads();
        if (cc + 2 < CH) load_stage(cc & 1, cc + 2);
    }
    cp_wait0();
    __syncthreads();

    // ---------- epilogue: residual + LayerNorm (+ producers) ----------
    float2* red = (float2*)(smem + RED_O);
    float2* mr  = (float2*)(smem + MR_O);
    float*  qsh = (float*)(smem + QSH_O);
    float*  pps = (float*)(smem + PPS_O);
    float*  w1s = (float*)(smem + W1S_O);
    float*  b1s = (float*)(smem + B1S_O);

    if constexpr (MODE == 0) {
#pragma unroll
        for (int i = 0; i < 16; i++) {
            int idx = tid + i * 256;                    // 4096 total
            int n = idx >> 9, f = idx & 511;
            w1s[f * 9 + n] = W1[idx];
        }
        b1s[tid]       = b1[tid];
        b1s[tid + 256] = b1[tid + 256];
    }

    int mcol = wn * 64 + (lane & 3) * 2;
    int r0l  = wm * 32 + (lane >> 2);

#pragma unroll
    for (int mi = 0; mi < 2; mi++) {
        float s0 = 0, q0 = 0, s1 = 0, q1 = 0;
        size_t ra = bm + r0l + mi * 16;
#pragma unroll
        for (int ni = 0; ni < 8; ni++) {
            int col = mcol + ni * 8;
            float2 x0 = *(const float2*)(g_x + ra * E_ + col);
            float2 x1 = *(const float2*)(g_x + (ra + 8) * E_ + col);
            float bcx = bias[col], bcy = bias[col + 1];
            float v0 = acc[mi][ni][0] + bcx + x0.x;
            float v1 = acc[mi][ni][1] + bcy + x0.y;
            float v2 = acc[mi][ni][2] + bcx + x1.x;
            float v3 = acc[mi][ni][3] + bcy + x1.y;
            acc[mi][ni][0] = v0; acc[mi][ni][1] = v1;
            acc[mi][ni][2] = v2; acc[mi][ni][3] = v3;
            s0 += v0 + v1; q0 += v0 * v0 + v1 * v1;
            s1 += v2 + v3; q1 += v2 * v2 + v3 * v3;
        }
#pragma unroll
        for (int o = 1; o <= 2; o <<= 1) {
            s0 += __shfl_xor_sync(0xffffffffu, s0, o);
            q0 += __shfl_xor_sync(0xffffffffu, q0, o);
            s1 += __shfl_xor_sync(0xffffffffu, s1, o);
            q1 += __shfl_xor_sync(0xffffffffu, q1, o);
        }
        if ((lane & 3) == 0) {
            int rl = r0l + mi * 16;
            red[rl * 4 + wn] = make_float2(s0, q0);
            red[(rl + 8) * 4 + wn] = make_float2(s1, q1);
        }
    }
    __syncthreads();
    if (tid < 64) {
        float s = 0, q = 0;
#pragma unroll
        for (int j = 0; j < 4; j++) { float2 t = red[tid * 4 + j]; s += t.x; q += t.y; }
        float mean = s * (1.0f / E_);
        float var  = q * (1.0f / E_) - mean * mean;
        mr[tid] = make_float2(mean, rsqrtf(var + 1e-5f));
    }
    __syncthreads();

    float cf0 = 0.f, cf1 = 0.f;
    if constexpr (MODE == 0) {
        int c = (lane & 3) * 2;
        cf0 = cosf(fTh[c]); cf1 = cosf(fTh[c + 1]);
    }
    float ps[8][2];
    if constexpr (MODE == 2) {
#pragma unroll
        for (int ni = 0; ni < 8; ni++) { ps[ni][0] = 0.f; ps[ni][1] = 0.f; }
    }

#pragma unroll
    for (int mi = 0; mi < 2; mi++) {
        int rl = r0l + mi * 16;
        float2 m0 = mr[rl], m1 = mr[rl + 8];
        size_t ra = bm + rl;
#pragma unroll
        for (int ni = 0; ni < 8; ni++) {
            int col = mcol + ni * 8;
            float gx = lnG[col], gy = lnG[col + 1];
            float bx = lnB[col], by = lnB[col + 1];
            float o0 = (acc[mi][ni][0] - m0.x) * m0.y * gx + bx;
            float o1 = (acc[mi][ni][1] - m0.x) * m0.y * gy + by;
            float o2 = (acc[mi][ni][2] - m1.x) * m1.y * gx + bx;
            float o3 = (acc[mi][ni][3] - m1.x) * m1.y * gy + by;
            if constexpr (MODE != 2) {
                *(float2*)(g_x + ra * E_ + col) = make_float2(o0, o1);
                *(float2*)(g_x + (ra + 8) * E_ + col) = make_float2(o2, o3);
            }
            if constexpr (MODE == 0) {
                if (wn == 0 && ni == 0) {
                    int c = (lane & 3) * 2;
                    qsh[rl * 8 + c]           = cosf(o0) * cf0;
                    qsh[rl * 8 + c + 1]       = cosf(o1) * cf1;
                    qsh[(rl + 8) * 8 + c]     = cosf(o2) * cf0;
                    qsh[(rl + 8) * 8 + c + 1] = cosf(o3) * cf1;
                }
            }
            if constexpr (MODE == 1) {
                float t0 = thN[col & 63], t1 = thN[(col + 1) & 63];
                float a0 = cosf(o0 + t0), a1 = cosf(o1 + t1);
                float a2 = cosf(o2 + t0), a3 = cosf(o3 + t1);
                __half p0 = __float2half_rn(a0), p1 = __float2half_rn(a1);
                __half p2 = __float2half_rn(a2), p3 = __float2half_rn(a3);
                *(__half2*)(g_ahi + ra * E_ + col) = __halves2half2(p0, p1);
                *(__half2*)(g_ahi + (ra + 8) * E_ + col) = __halves2half2(p2, p3);
                *(__half2*)(g_alo + ra * E_ + col) =
                    __halves2half2(__float2half_rn(a0 - __half2float(p0)),
                                   __float2half_rn(a1 - __half2float(p1)));
                *(__half2*)(g_alo + (ra + 8) * E_ + col) =
                    __halves2half2(__float2half_rn(a2 - __half2float(p2)),
                                   __float2half_rn(a3 - __half2float(p3)));
            }
            if constexpr (MODE == 2) {
                ps[ni][0] += o0 + o2;
                ps[ni][1] += o1 + o3;
            }
        }
    }

    if constexpr (MODE == 0) {
        // ---- h = relu(q @ W1 + b1) -> single fp16, write g_hh ----
        __syncthreads();                       // qsh / w1s / b1s ready
        int hrow = tid >> 2;                   // 0..63
        int cg   = tid & 3;
        float qr[8];
#pragma unroll
        for (int n = 0; n < 8; n++) qr[n] = qsh[hrow * 8 + n];
        size_t ra = bm + hrow;
#pragma unroll
        for (int jj = 0; jj < 16; jj++) {
            int f0 = cg * 8 + jj * 32;
            __half2 hp[4];
#pragma unroll
            for (int v = 0; v < 4; v++) {
                int f = f0 + v * 2;
                float h0 = b1s[f], h1 = b1s[f + 1];
#pragma unroll
                for (int n = 0; n < 8; n++) {
                    h0 += qr[n] * w1s[f * 9 + n];
                    h1 += qr[n] * w1s[(f + 1) * 9 + n];
                }
                hp[v] = __halves2half2(__float2half_rn(fmaxf(h0, 0.f)),
                                       __float2half_rn(fmaxf(h1, 0.f)));
            }
            *(uint4*)(g_hh + ra * FFN_ + f0) = *(uint4*)hp;
        }
    }

    if constexpr (MODE == 2) {
#pragma unroll
        for (int ni = 0; ni < 8; ni++)
#pragma unroll
            for (int o = 4; o <= 16; o <<= 1) {
                ps[ni][0] += __shfl_xor_sync(0xffffffffu, ps[ni][0], o);
                ps[ni][1] += __shfl_xor_sync(0xffffffffu, ps[ni][1], o);
            }
        if (lane < 4) {
#pragma unroll
            for (int ni = 0; ni < 8; ni++) {
                pps[wm * 256 + mcol + ni * 8]     = ps[ni][0];
                pps[wm * 256 + mcol + ni * 8 + 1] = ps[ni][1];
            }
        }
        __syncthreads();
        if (tid < 256) g_pp[blockIdx.x * 256 + tid] = pps[tid] + pps[256 + tid];
    }
}

// ---------------- classifier -------------------------------------------------
__global__ void k_cls(const float* __restrict__ w, const float* __restrict__ cb,
                      float* __restrict__ out) {
    __shared__ float sh[16];
    int b = blockIdx.x, e = threadIdx.x;
    float p = 0.f;
#pragma unroll 8
    for (int j = 0; j < 32; j++) p += g_pp[(b * 32 + j) * E_ + e];
    p *= (1.0f / (float)S_);
    float s0 = p * w[e * 2], s1 = p * w[e * 2 + 1];
    for (int o = 16; o > 0; o >>= 1) {
        s0 += __shfl_xor_sync(0xffffffffu, s0, o);
        s1 += __shfl_xor_sync(0xffffffffu, s1, o);
    }
    int wi = e >> 5;
    if ((e & 31) == 0) { sh[wi * 2] = s0; sh[wi * 2 + 1] = s1; }
    __syncthreads();
    if (e == 0) {
        float t0 = 0, t1 = 0;
#pragma unroll
        for (int j = 0; j < 8; j++) { t0 += sh[j * 2]; t1 += sh[j * 2 + 1]; }
        out[b * 2]     = t0 + cb[0];
        out[b * 2 + 1] = t1 + cb[1];
    }
}

// ---------------- host launcher ----------------------------------------------
extern "C" void kernel_launch(void* const* d_in, const int* in_sizes, int n_in,
                              void* d_out, int out_size) {
    const int*   tokens     = (const int*)d_in[0];
    const float* embed      = (const float*)d_in[1];
    const float* attn_theta = (const float*)d_in[2];
    const float* combine_w  = (const float*)d_in[3];
    const float* combine_b  = (const float*)d_in[4];
    const float* ffn_theta  = (const float*)d_in[5];
    const float* lin1_w     = (const float*)d_in[6];
    const float* lin1_b     = (const float*)d_in[7];
    const float* lin2_w     = (const float*)d_in[8];
    const float* lin2_b     = (const float*)d_in[9];
    const float* ln1_g      = (const float*)d_in[10];
    const float* ln1_b      = (const float*)d_in[11];
    const float* ln2_g      = (const float*)d_in[12];
    const float* ln2_b      = (const float*)d_in[13];
    const float* cls_w      = (const float*)d_in[14];
    const float* cls_b      = (const float*)d_in[15];
    float* out = (float*)d_out;

    __half *ahi, *alo, *hh, *wh;
    cudaGetSymbolAddress((void**)&ahi, g_ahi);
    cudaGetSymbolAddress((void**)&alo, g_alo);
    cudaGetSymbolAddress((void**)&hh,  g_hh);
    cudaGetSymbolAddress((void**)&wh,  g_wh);

    cudaFuncSetAttribute(k_gf<256, 0, 2>, cudaFuncAttributeMaxDynamicSharedMemorySize, SME_ATT);
    cudaFuncSetAttribute(k_gf<512, 1, 1>, cudaFuncAttributeMaxDynamicSharedMemorySize, SME_FFN);
    cudaFuncSetAttribute(k_gf<512, 2, 1>, cudaFuncAttributeMaxDynamicSharedMemorySize, SME_FFN);

    k_embed<<<M_, 256>>>(tokens, embed, attn_theta);
    k_convw<<<dim3(256, 4), 256>>>(combine_w, lin2_w);

    // layer 0
    k_gf<256, 0, 2><<<M_ / 64, 256, SME_ATT>>>(
        ahi, alo, wh + 0 * 131072, combine_b + 0 * E_,
        ln1_g + 0 * E_, ln1_b + 0 * E_, nullptr,
        ffn_theta + 0 * NQ_, lin1_w + 0 * NQ_ * FFN_, lin1_b + 0 * FFN_);
    k_gf<512, 1, 1><<<M_ / 64, 256, SME_FFN>>>(
        hh, nullptr, wh + 2 * 131072, lin2_b + 0 * E_,
        ln2_g + 0 * E_, ln2_b + 0 * E_, attn_theta + 1 * 64,
        nullptr, nullptr, nullptr);
    // layer 1
    k_gf<256, 0, 2><<<M_ / 64, 256, SME_ATT>>>(
        ahi, alo, wh + 1 * 131072, combine_b + 1 * E_,
        ln1_g + 1 * E_, ln1_b + 1 * E_, nullptr,
        ffn_theta + 1 * NQ_, lin1_w + 1 * NQ_ * FFN_, lin1_b + 1 * FFN_);
    k_gf<512, 2, 1><<<M_ / 64, 256, SME_FFN>>>(
        hh, nullptr, wh + 3 * 131072, lin2_b + 1 * E_,
        ln2_g + 1 * E_, ln2_b + 1 * E_, nullptr,
        nullptr, nullptr, nullptr);

    k_cls<<<B_, 256>>>(cls_w, cls_b, out);
}

// round 11
// speedup vs baseline: 1.1640x; 1.0260x over previous
#include <cuda_runtime.h>
#include <cuda_fp16.h>
#include <cstdint>
#include <math.h>

#define B_   16
#define S_   2048
#define E_   256
#define L_   2
#define NQ_  8
#define FFN_ 512
#define C_   2
#define M_   (B_*S_)   // 32768 rows

// ---------------- scratch (__device__ globals; no allocations) ---------------
__device__ float g_x[(size_t)M_*E_];                      // 32 MB
__device__ __align__(128) __half g_ahi[(size_t)M_*E_];    // 16 MB  attn A hi
__device__ __align__(128) __half g_alo[(size_t)M_*E_];    // 16 MB  attn A lo
__device__ __align__(128) __half g_wh[4*256*512];         // Wt[n][k] fp16
__device__ float g_pp[512*E_];                            // pool partials

// ---------------- smem layout (bytes) ----------------------------------------
// stages: [0, 49152)  (phase A: 2x24576; phase B: 2x20480)
#define W1S_O  49152    // [8][512] float, [n][f] layout, 16384 B
#define B1S_O  65536    // [512] float, 2048 B
#define QSH_O  67584    // [64][8] float, 2048 B
#define RED_O  69632    // [64][4] float2, 2048 B
#define MR_O   71680    // [64] float2, 512 B
#define PPS_O  72192    // [2][256] float, 2048 B
#define SME_T  74240

// ---------------- PTX helpers ------------------------------------------------
__device__ __forceinline__ uint32_t s2u(const void* p) {
    uint32_t a;
    asm("{ .reg .u64 t; cvta.to.shared.u64 t, %1; cvt.u32.u64 %0, t; }"
        : "=r"(a) : "l"(p));
    return a;
}
__device__ __forceinline__ void cp16(uint32_t dst, const void* src) {
    asm volatile("cp.async.cg.shared.global [%0], [%1], 16;" :: "r"(dst), "l"(src));
}
__device__ __forceinline__ void cp_commit() {
    asm volatile("cp.async.commit_group;" ::: "memory");
}
__device__ __forceinline__ void cp_wait1() {
    asm volatile("cp.async.wait_group 1;" ::: "memory");
}
__device__ __forceinline__ void cp_wait0() {
    asm volatile("cp.async.wait_group 0;" ::: "memory");
}
__device__ __forceinline__ void ldm_x4(uint32_t& r0, uint32_t& r1, uint32_t& r2,
                                       uint32_t& r3, uint32_t addr) {
    asm volatile("ldmatrix.sync.aligned.m8n8.x4.shared.b16 {%0,%1,%2,%3}, [%4];"
                 : "=r"(r0), "=r"(r1), "=r"(r2), "=r"(r3) : "r"(addr));
}
__device__ __forceinline__ void mma16816(float* c, uint32_t a0, uint32_t a1,
                                         uint32_t a2, uint32_t a3,
                                         uint32_t b0, uint32_t b1) {
    asm volatile(
        "mma.sync.aligned.m16n8k16.row.col.f32.f16.f16.f32 "
        "{%0,%1,%2,%3}, {%4,%5,%6,%7}, {%8,%9}, {%0,%1,%2,%3};"
        : "+f"(c[0]), "+f"(c[1]), "+f"(c[2]), "+f"(c[3])
        : "r"(a0), "r"(a1), "r"(a2), "r"(a3), "r"(b0), "r"(b1));
}

// ---------------- embed + PE + fused prep for layer-0 attn -------------------
__global__ void k_embed(const int* __restrict__ tok, const float* __restrict__ emb,
                        const float* __restrict__ th) {
    int row = blockIdx.x;
    int e   = threadIdx.x;
    int t   = tok[row];
    int s   = row & (S_ - 1);
    int i   = e >> 1;
    float freq = expf(-(float)(2 * i) * (9.210340371976184f / (float)E_));
    float ang  = (float)s * freq;
    float pe   = (e & 1) ? cosf(ang) : sinf(ang);
    size_t idx = (size_t)row * E_ + e;
    float x = emb[(size_t)t * E_ + e] + pe;
    g_x[idx] = x;
    float a = cosf(x + th[e & 63]);
    __half hi = __float2half_rn(a);
    g_ahi[idx] = hi;
    g_alo[idx] = __float2half_rn(a - __half2float(hi));
}

// ---------------- weight convert + transpose (fp16) --------------------------
__global__ void k_convw(const float* __restrict__ cw, const float* __restrict__ l2w) {
    int slot = blockIdx.y;
    int n    = blockIdx.x;
    int K    = (slot < 2) ? 256 : 512;
    const float* src = (slot < 2) ? (cw + (size_t)slot * E_ * E_)
                                  : (l2w + (size_t)(slot - 2) * FFN_ * E_);
    for (int k = threadIdx.x; k < K; k += 256) {
        float w = src[(size_t)k * E_ + n];
        g_wh[(size_t)slot * 131072 + (size_t)n * K + k] = __float2half_rn(w);
    }
}

// ---------------- GEMM phase: BM=64, BN=256, BK=32, 256 thr (2Mx4N warps) ----
// TERMS=2: D += Ah*W + Al*W (A from global). COMPA: A chunk computed from
// q @ W1 + b1 (relu, fp16) in-CTA. 64B smem rows, XOR-4 swizzle, 2-stage.
template <int K, int TERMS, bool COMPA>
__device__ __forceinline__ void run_gemm(
    float (&acc)[2][8][4], char* smem, uint32_t sb, size_t bm,
    const __half* __restrict__ Agh, const __half* __restrict__ Agl,
    const __half* __restrict__ W,
    const float* qsh, const float* w1s, const float* b1s) {
    constexpr int CH    = K >> 5;
    constexpr int A_LO  = 4096;
    constexpr int W_O   = (TERMS == 2) ? 8192 : 4096;
    constexpr int STAGE = W_O + 16384;
    int tid = threadIdx.x, lane = tid & 31, wid = tid >> 5;
    int wm = wid >> 2, wn = wid & 3;
    int part = tid & 3, rb = tid >> 2;                    // rb 0..63
    uint32_t swc = (uint32_t)(part ^ ((rb >> 1) & 3)) << 4;

    auto load_stage = [&](int st, int ch) {
        uint32_t dst = sb + st * STAGE;
        int kk = ch << 5;
        if constexpr (!COMPA) {
            cp16(dst + rb * 64 + swc, Agh + (bm + rb) * (size_t)K + kk + part * 8);
            if constexpr (TERMS == 2)
                cp16(dst + A_LO + rb * 64 + swc,
                     Agl + (bm + rb) * (size_t)K + kk + part * 8);
        }
#pragma unroll
        for (int i = 0; i < 4; i++) {
            int r = rb + i * 64;
            cp16(dst + W_O + r * 64 + swc, W + (size_t)r * K + kk + part * 8);
        }
        cp_commit();
    };

    auto comp_h = [&](int st, int ch) {
        if constexpr (COMPA) {
            char* dst = smem + st * STAGE;
            int f0 = (ch << 5) + part * 8;
            float qr[8];
#pragma unroll
            for (int n = 0; n < 8; n++) qr[n] = qsh[rb * 8 + n];
            __half2 hp[4];
#pragma unroll
            for (int jj = 0; jj < 4; jj++) {
                float hv[2];
#pragma unroll
                for (int u = 0; u < 2; u++) {
                    int f = f0 + jj * 2 + u;
                    float h = b1s[f];
#pragma unroll
                    for (int n = 0; n < 8; n++) h += qr[n] * w1s[n * 512 + f];
                    hv[u] = fmaxf(h, 0.f);
                }
                hp[jj] = __halves2half2(__float2half_rn(hv[0]),
                                        __float2half_rn(hv[1]));
            }
            *(uint4*)(dst + rb * 64 + swc) = *(uint4*)hp;
        }
    };

    load_stage(0, 0); comp_h(0, 0);
    load_stage(1, 1); comp_h(1, 1);

    uint32_t rowA = wm * 32 + (lane & 15);
    uint32_t rxA  = (rowA >> 1) & 3;
    uint32_t cA   = (uint32_t)lane >> 4;
    uint32_t rowB = wn * 64 + ((lane >> 4) & 1) * 8 + (lane & 7);
    uint32_t rxB  = (rowB >> 1) & 3;
    uint32_t cB   = ((uint32_t)lane >> 3) & 1;

    for (int cc = 0; cc < CH; cc++) {
        if (cc + 1 < CH) cp_wait1(); else cp_wait0();
        __syncthreads();
        uint32_t stg = sb + (cc & 1) * STAGE;
        uint32_t aB  = stg + rowA * 64;
        uint32_t bB  = stg + W_O + rowB * 64;

#pragma unroll
        for (int kb = 0; kb < 2; kb++) {
            uint32_t colA = (((uint32_t)(kb * 2) + cA) ^ rxA) << 4;
            uint32_t colB = (((uint32_t)(kb * 2) + cB) ^ rxB) << 4;
            uint32_t b[16];
#pragma unroll
            for (int n2 = 0; n2 < 4; n2++)
                ldm_x4(b[n2*4], b[n2*4+1], b[n2*4+2], b[n2*4+3],
                       bB + n2 * 1024 + colB);
            uint32_t h0[2], h1[2], h2[2], h3[2];
#pragma unroll
            for (int mi = 0; mi < 2; mi++)
                ldm_x4(h0[mi], h1[mi], h2[mi], h3[mi], aB + mi * 1024 + colA);
#pragma unroll
            for (int mi = 0; mi < 2; mi++)
#pragma unroll
                for (int n2 = 0; n2 < 4; n2++) {
                    mma16816(acc[mi][n2*2],   h0[mi], h1[mi], h2[mi], h3[mi],
                             b[n2*4],   b[n2*4+1]);
                    mma16816(acc[mi][n2*2+1], h0[mi], h1[mi], h2[mi], h3[mi],
                             b[n2*4+2], b[n2*4+3]);
                }
            if constexpr (TERMS == 2) {
#pragma unroll
                for (int mi = 0; mi < 2; mi++)
                    ldm_x4(h0[mi], h1[mi], h2[mi], h3[mi],
                           aB + A_LO + mi * 1024 + colA);
#pragma unroll
                for (int mi = 0; mi < 2; mi++)
#pragma unroll
                    for (int n2 = 0; n2 < 4; n2++) {
                        mma16816(acc[mi][n2*2],   h0[mi], h1[mi], h2[mi], h3[mi],
                                 b[n2*4],   b[n2*4+1]);
                        mma16816(acc[mi][n2*2+1], h0[mi], h1[mi], h2[mi], h3[mi],
                                 b[n2*4+2], b[n2*4+3]);
                    }
            }
        }
        __syncthreads();
        if (cc + 2 < CH) { load_stage(cc & 1, cc + 2); comp_h(cc & 1, cc + 2); }
    }
}

// ---------------- epilogue: residual + LN (+ producer) -----------------------
// PROD 0: write g_x + q->qsh.  PROD 1: write g_x + next-layer A hi/lo.
// PROD 2: pool partials only.
template <int PROD>
__device__ __forceinline__ void epilogue(
    float (&acc)[2][8][4], char* smem, size_t bm,
    const float* __restrict__ bias,
    const float* __restrict__ lnG, const float* __restrict__ lnB,
    const float* __restrict__ fTh, const float* __restrict__ thN) {
    float2* red = (float2*)(smem + RED_O);
    float2* mr  = (float2*)(smem + MR_O);
    float*  qsh = (float*)(smem + QSH_O);
    float*  pps = (float*)(smem + PPS_O);
    int tid = threadIdx.x, lane = tid & 31, wid = tid >> 5;
    int wm = wid >> 2, wn = wid & 3;
    int mcol = wn * 64 + (lane & 3) * 2;
    int r0l  = wm * 32 + (lane >> 2);

#pragma unroll
    for (int mi = 0; mi < 2; mi++) {
        float s0 = 0, q0 = 0, s1 = 0, q1 = 0;
        size_t ra = bm + r0l + mi * 16;
#pragma unroll
        for (int ni = 0; ni < 8; ni++) {
            int col = mcol + ni * 8;
            float2 x0 = *(const float2*)(g_x + ra * E_ + col);
            float2 x1 = *(const float2*)(g_x + (ra + 8) * E_ + col);
            float bcx = bias[col], bcy = bias[col + 1];
            float v0 = acc[mi][ni][0] + bcx + x0.x;
            float v1 = acc[mi][ni][1] + bcy + x0.y;
            float v2 = acc[mi][ni][2] + bcx + x1.x;
            float v3 = acc[mi][ni][3] + bcy + x1.y;
            acc[mi][ni][0] = v0; acc[mi][ni][1] = v1;
            acc[mi][ni][2] = v2; acc[mi][ni][3] = v3;
            s0 += v0 + v1; q0 += v0 * v0 + v1 * v1;
            s1 += v2 + v3; q1 += v2 * v2 + v3 * v3;
        }
#pragma unroll
        for (int o = 1; o <= 2; o <<= 1) {
            s0 += __shfl_xor_sync(0xffffffffu, s0, o);
            q0 += __shfl_xor_sync(0xffffffffu, q0, o);
            s1 += __shfl_xor_sync(0xffffffffu, s1, o);
            q1 += __shfl_xor_sync(0xffffffffu, q1, o);
        }
        if ((lane & 3) == 0) {
            int rl = r0l + mi * 16;
            red[rl * 4 + wn] = make_float2(s0, q0);
            red[(rl + 8) * 4 + wn] = make_float2(s1, q1);
        }
    }
    __syncthreads();
    if (tid < 64) {
        float s = 0, q = 0;
#pragma unroll
        for (int j = 0; j < 4; j++) { float2 t = red[tid * 4 + j]; s += t.x; q += t.y; }
        float mean = s * (1.0f / E_);
        float var  = q * (1.0f / E_) - mean * mean;
        mr[tid] = make_float2(mean, rsqrtf(var + 1e-5f));
    }
    __syncthreads();

    float cf0 = 0.f, cf1 = 0.f;
    if constexpr (PROD == 0) {
        int c = (lane & 3) * 2;
        cf0 = cosf(fTh[c]); cf1 = cosf(fTh[c + 1]);
    }
    float ps[8][2];
    if constexpr (PROD == 2) {
#pragma unroll
        for (int ni = 0; ni < 8; ni++) { ps[ni][0] = 0.f; ps[ni][1] = 0.f; }
    }

#pragma unroll
    for (int mi = 0; mi < 2; mi++) {
        int rl = r0l + mi * 16;
        float2 m0 = mr[rl], m1 = mr[rl + 8];
        size_t ra = bm + rl;
#pragma unroll
        for (int ni = 0; ni < 8; ni++) {
            int col = mcol + ni * 8;
            float gx = lnG[col], gy = lnG[col + 1];
            float bx = lnB[col], by = lnB[col + 1];
            float o0 = (acc[mi][ni][0] - m0.x) * m0.y * gx + bx;
            float o1 = (acc[mi][ni][1] - m0.x) * m0.y * gy + by;
            float o2 = (acc[mi][ni][2] - m1.x) * m1.y * gx + bx;
            float o3 = (acc[mi][ni][3] - m1.x) * m1.y * gy + by;
            if constexpr (PROD != 2) {
                *(float2*)(g_x + ra * E_ + col) = make_float2(o0, o1);
                *(float2*)(g_x + (ra + 8) * E_ + col) = make_float2(o2, o3);
            }
            if constexpr (PROD == 0) {
                if (wn == 0 && ni == 0) {
                    int c = (lane & 3) * 2;
                    qsh[rl * 8 + c]           = cosf(o0) * cf0;
                    qsh[rl * 8 + c + 1]       = cosf(o1) * cf1;
                    qsh[(rl + 8) * 8 + c]     = cosf(o2) * cf0;
                    qsh[(rl + 8) * 8 + c + 1] = cosf(o3) * cf1;
                }
            }
            if constexpr (PROD == 1) {
                float t0 = thN[col & 63], t1 = thN[(col + 1) & 63];
                float a0 = cosf(o0 + t0), a1 = cosf(o1 + t1);
                float a2 = cosf(o2 + t0), a3 = cosf(o3 + t1);
                __half p0 = __float2half_rn(a0), p1 = __float2half_rn(a1);
                __half p2 = __float2half_rn(a2), p3 = __float2half_rn(a3);
                *(__half2*)(g_ahi + ra * E_ + col) = __halves2half2(p0, p1);
                *(__half2*)(g_ahi + (ra + 8) * E_ + col) = __halves2half2(p2, p3);
                *(__half2*)(g_alo + ra * E_ + col) =
                    __halves2half2(__float2half_rn(a0 - __half2float(p0)),
                                   __float2half_rn(a1 - __half2float(p1)));
                *(__half2*)(g_alo + (ra + 8) * E_ + col) =
                    __halves2half2(__float2half_rn(a2 - __half2float(p2)),
                                   __float2half_rn(a3 - __half2float(p3)));
            }
            if constexpr (PROD == 2) {
                ps[ni][0] += o0 + o2;
                ps[ni][1] += o1 + o3;
            }
        }
    }

    if constexpr (PROD == 2) {
#pragma unroll
        for (int ni = 0; ni < 8; ni++)
#pragma unroll
            for (int o = 4; o <= 16; o <<= 1) {
                ps[ni][0] += __shfl_xor_sync(0xffffffffu, ps[ni][0], o);
                ps[ni][1] += __shfl_xor_sync(0xffffffffu, ps[ni][1], o);
            }
        if (lane < 4) {
#pragma unroll
            for (int ni = 0; ni < 8; ni++) {
                pps[wm * 256 + mcol + ni * 8]     = ps[ni][0];
                pps[wm * 256 + mcol + ni * 8 + 1] = ps[ni][1];
            }
        }
        __syncthreads();
        if (tid < 256) g_pp[blockIdx.x * 256 + tid] = pps[tid] + pps[256 + tid];
    }
}

// ---------------- fused transformer layer: attn GEMM -> LN1 -> ffn -> LN2 ----
template <int LAYER>
__global__ void __launch_bounds__(256, 2)
k_layer(const __half* __restrict__ Agh, const __half* __restrict__ Agl,
        const __half* __restrict__ Wa, const __half* __restrict__ Wf,
        const float* __restrict__ cb,
        const float* __restrict__ ln1g, const float* __restrict__ ln1b,
        const float* __restrict__ fTh,
        const float* __restrict__ W1, const float* __restrict__ b1,
        const float* __restrict__ l2b,
        const float* __restrict__ ln2g, const float* __restrict__ ln2b,
        const float* __restrict__ thN) {
    extern __shared__ __align__(16) char smem[];
    uint32_t sb = s2u(smem);
    int tid = threadIdx.x;
    size_t bm = (size_t)blockIdx.x * 64;

    float* w1s = (float*)(smem + W1S_O);
    float* b1s = (float*)(smem + B1S_O);
    float* qsh = (float*)(smem + QSH_O);

    // stage W1 ([n][f] layout, same as global) + b1 — consumed in phase B
#pragma unroll
    for (int i = 0; i < 16; i++) w1s[tid + i * 256] = W1[tid + i * 256];
    b1s[tid]       = b1[tid];
    b1s[tid + 256] = b1[tid + 256];

    float acc[2][8][4];
#pragma unroll
    for (int i = 0; i < 2; i++)
#pragma unroll
        for (int j = 0; j < 8; j++)
#pragma unroll
            for (int c = 0; c < 4; c++) acc[i][j][c] = 0.f;

    // phase A: attn GEMM (2-term, K=256)
    run_gemm<256, 2, false>(acc, smem, sb, bm, Agh, Agl, Wa,
                            nullptr, nullptr, nullptr);
    epilogue<0>(acc, smem, bm, cb, ln1g, ln1b, fTh, nullptr);
    __syncthreads();   // qsh ready for comp_h

    // phase B: ffn GEMM (1-term, K=512, A computed in-CTA)
#pragma unroll
    for (int i = 0; i < 2; i++)
#pragma unroll
        for (int j = 0; j < 8; j++)
#pragma unroll
            for (int c = 0; c < 4; c++) acc[i][j][c] = 0.f;
    run_gemm<512, 1, true>(acc, smem, sb, bm, nullptr, nullptr, Wf,
                           qsh, w1s, b1s);
    if constexpr (LAYER == 0)
        epilogue<1>(acc, smem, bm, l2b, ln2g, ln2b, nullptr, thN);
    else
        epilogue<2>(acc, smem, bm, l2b, ln2g, ln2b, nullptr, nullptr);
}

// ---------------- classifier -------------------------------------------------
__global__ void k_cls(const float* __restrict__ w, const float* __restrict__ cb,
                      float* __restrict__ out) {
    __shared__ float sh[16];
    int b = blockIdx.x, e = threadIdx.x;
    float p = 0.f;
#pragma unroll 8
    for (int j = 0; j < 32; j++) p += g_pp[(b * 32 + j) * E_ + e];
    p *= (1.0f / (float)S_);
    float s0 = p * w[e * 2], s1 = p * w[e * 2 + 1];
    for (int o = 16; o > 0; o >>= 1) {
        s0 += __shfl_xor_sync(0xffffffffu, s0, o);
        s1 += __shfl_xor_sync(0xffffffffu, s1, o);
    }
    int wi = e >> 5;
    if ((e & 31) == 0) { sh[wi * 2] = s0; sh[wi * 2 + 1] = s1; }
    __syncthreads();
    if (e == 0) {
        float t0 = 0, t1 = 0;
#pragma unroll
        for (int j = 0; j < 8; j++) { t0 += sh[j * 2]; t1 += sh[j * 2 + 1]; }
        out[b * 2]     = t0 + cb[0];
        out[b * 2 + 1] = t1 + cb[1];
    }
}

// ---------------- host launcher ----------------------------------------------
extern "C" void kernel_launch(void* const* d_in, const int* in_sizes, int n_in,
                              void* d_out, int out_size) {
    const int*   tokens     = (const int*)d_in[0];
    const float* embed      = (const float*)d_in[1];
    const float* attn_theta = (const float*)d_in[2];
    const float* combine_w  = (const float*)d_in[3];
    const float* combine_b  = (const float*)d_in[4];
    const float* ffn_theta  = (const float*)d_in[5];
    const float* lin1_w     = (const float*)d_in[6];
    const float* lin1_b     = (const float*)d_in[7];
    const float* lin2_w     = (const float*)d_in[8];
    const float* lin2_b     = (const float*)d_in[9];
    const float* ln1_g      = (const float*)d_in[10];
    const float* ln1_b      = (const float*)d_in[11];
    const float* ln2_g      = (const float*)d_in[12];
    const float* ln2_b      = (const float*)d_in[13];
    const float* cls_w      = (const float*)d_in[14];
    const float* cls_b      = (const float*)d_in[15];
    float* out = (float*)d_out;

    __half *ahi, *alo, *wh;
    cudaGetSymbolAddress((void**)&ahi, g_ahi);
    cudaGetSymbolAddress((void**)&alo, g_alo);
    cudaGetSymbolAddress((void**)&wh,  g_wh);

    cudaFuncSetAttribute(k_layer<0>, cudaFuncAttributeMaxDynamicSharedMemorySize, SME_T);
    cudaFuncSetAttribute(k_layer<1>, cudaFuncAttributeMaxDynamicSharedMemorySize, SME_T);

    k_embed<<<M_, 256>>>(tokens, embed, attn_theta);
    k_convw<<<dim3(256, 4), 256>>>(combine_w, lin2_w);

    k_layer<0><<<M_ / 64, 256, SME_T>>>(
        ahi, alo, wh + 0 * 131072, wh + 2 * 131072,
        combine_b, ln1_g, ln1_b,
        ffn_theta, lin1_w, lin1_b,
        lin2_b, ln2_g, ln2_b, attn_theta + 64);
    k_layer<1><<<M_ / 64, 256, SME_T>>>(
        ahi, alo, wh + 1 * 131072, wh + 3 * 131072,
        combine_b + E_, ln1_g + E_, ln1_b + E_,
        ffn_theta + NQ_, lin1_w + NQ_ * FFN_, lin1_b + FFN_,
        lin2_b + E_, ln2_g + E_, ln2_b + E_, nullptr);

    k_cls<<<B_, 256>>>(cls_w, cls_b, out);
}

// round 12
// speedup vs baseline: 1.1798x; 1.0135x over previous
#include <cuda_runtime.h>
#include <cuda_fp16.h>
#include <cstdint>
#include <math.h>

#define B_   16
#define S_   2048
#define E_   256
#define L_   2
#define NQ_  8
#define FFN_ 512
#define C_   2
#define M_   (B_*S_)   // 32768 rows

// ---------------- scratch (__device__ globals; no allocations) ---------------
__device__ float g_x[(size_t)M_*E_];                      // 32 MB
__device__ __align__(128) __half g_ahi[(size_t)M_*E_];    // 16 MB  attn A hi
__device__ __align__(128) __half g_alo[(size_t)M_*E_];    // 16 MB  attn A lo
__device__ __align__(128) __half g_wh[4*256*512];         // Wt[n][k] fp16
__device__ float g_pp[512*E_];                            // pool partials

// ---------------- smem layout (bytes) ----------------------------------------
// stages: [0, 73728)  (phase A: 3x24576; phase B: 3x20480)
#define W1S_O  73728    // [8][512] float, [n][f] layout, 16384 B
#define B1S_O  90112    // [512] float, 2048 B
#define QSH_O  92160    // [64][8] float, 2048 B
#define RED_O  94208    // [64][4] float2, 2048 B
#define MR_O   96256    // [64] float2, 512 B
#define PPS_O  96768    // [2][256] float, 2048 B
#define SME_T  98816

// ---------------- PTX helpers ------------------------------------------------
__device__ __forceinline__ uint32_t s2u(const void* p) {
    uint32_t a;
    asm("{ .reg .u64 t; cvta.to.shared.u64 t, %1; cvt.u32.u64 %0, t; }"
        : "=r"(a) : "l"(p));
    return a;
}
__device__ __forceinline__ void cp16(uint32_t dst, const void* src) {
    asm volatile("cp.async.cg.shared.global [%0], [%1], 16;" :: "r"(dst), "l"(src));
}
__device__ __forceinline__ void cp_commit() {
    asm volatile("cp.async.commit_group;" ::: "memory");
}
__device__ __forceinline__ void cp_wait1() {
    asm volatile("cp.async.wait_group 1;" ::: "memory");
}
__device__ __forceinline__ void cp_wait0() {
    asm volatile("cp.async.wait_group 0;" ::: "memory");
}
__device__ __forceinline__ void ldm_x4(uint32_t& r0, uint32_t& r1, uint32_t& r2,
                                       uint32_t& r3, uint32_t addr) {
    asm volatile("ldmatrix.sync.aligned.m8n8.x4.shared.b16 {%0,%1,%2,%3}, [%4];"
                 : "=r"(r0), "=r"(r1), "=r"(r2), "=r"(r3) : "r"(addr));
}
__device__ __forceinline__ void mma16816(float* c, uint32_t a0, uint32_t a1,
                                         uint32_t a2, uint32_t a3,
                                         uint32_t b0, uint32_t b1) {
    asm volatile(
        "mma.sync.aligned.m16n8k16.row.col.f32.f16.f16.f32 "
        "{%0,%1,%2,%3}, {%4,%5,%6,%7}, {%8,%9}, {%0,%1,%2,%3};"
        : "+f"(c[0]), "+f"(c[1]), "+f"(c[2]), "+f"(c[3])
        : "r"(a0), "r"(a1), "r"(a2), "r"(a3), "r"(b0), "r"(b1));
}

// ---------------- embed + PE + fused prep for layer-0 attn -------------------
__global__ void k_embed(const int* __restrict__ tok, const float* __restrict__ emb,
                        const float* __restrict__ th) {
    int row = blockIdx.x;
    int e   = threadIdx.x;
    int t   = tok[row];
    int s   = row & (S_ - 1);
    int i   = e >> 1;
    float freq = expf(-(float)(2 * i) * (9.210340371976184f / (float)E_));
    float ang  = (float)s * freq;
    float pe   = (e & 1) ? cosf(ang) : sinf(ang);
    size_t idx = (size_t)row * E_ + e;
    float x = emb[(size_t)t * E_ + e] + pe;
    g_x[idx] = x;
    float a = cosf(x + th[e & 63]);
    __half hi = __float2half_rn(a);
    g_ahi[idx] = hi;
    g_alo[idx] = __float2half_rn(a - __half2float(hi));
}

// ---------------- weight convert + transpose (fp16) --------------------------
__global__ void k_convw(const float* __restrict__ cw, const float* __restrict__ l2w) {
    int slot = blockIdx.y;
    int n    = blockIdx.x;
    int K    = (slot < 2) ? 256 : 512;
    const float* src = (slot < 2) ? (cw + (size_t)slot * E_ * E_)
                                  : (l2w + (size_t)(slot - 2) * FFN_ * E_);
    for (int k = threadIdx.x; k < K; k += 256) {
        float w = src[(size_t)k * E_ + n];
        g_wh[(size_t)slot * 131072 + (size_t)n * K + k] = __float2half_rn(w);
    }
}

// ---------------- GEMM phase: BM=64, BN=256, BK=32, 256 thr (2Mx4N warps) ----
// TERMS=2: D += Ah*W + Al*W (A from global). COMPA: A chunk computed from
// q @ W1 + b1 (relu, fp16) in-CTA. 64B smem rows, XOR-4 swizzle.
// 3-stage pipeline: ONE barrier per chunk (loads for cc+2 target an idle
// buffer, so no trailing sync is needed).
template <int K, int TERMS, bool COMPA>
__device__ __forceinline__ void run_gemm(
    float (&acc)[2][8][4], char* smem, uint32_t sb, size_t bm,
    const __half* __restrict__ Agh, const __half* __restrict__ Agl,
    const __half* __restrict__ W,
    const float* qsh, const float* w1s, const float* b1s) {
    constexpr int CH    = K >> 5;
    constexpr int A_LO  = 4096;
    constexpr int W_O   = (TERMS == 2) ? 8192 : 4096;
    constexpr int STAGE = W_O + 16384;
    int tid = threadIdx.x, lane = tid & 31, wid = tid >> 5;
    int wm = wid >> 2, wn = wid & 3;
    int part = tid & 3, rb = tid >> 2;                    // rb 0..63
    uint32_t swc = (uint32_t)(part ^ ((rb >> 1) & 3)) << 4;

    auto load_stage = [&](int st, int ch) {
        uint32_t dst = sb + st * STAGE;
        int kk = ch << 5;
        if constexpr (!COMPA) {
            cp16(dst + rb * 64 + swc, Agh + (bm + rb) * (size_t)K + kk + part * 8);
            if constexpr (TERMS == 2)
                cp16(dst + A_LO + rb * 64 + swc,
                     Agl + (bm + rb) * (size_t)K + kk + part * 8);
        }
#pragma unroll
        for (int i = 0; i < 4; i++) {
            int r = rb + i * 64;
            cp16(dst + W_O + r * 64 + swc, W + (size_t)r * K + kk + part * 8);
        }
        cp_commit();
    };

    auto comp_h = [&](int st, int ch) {
        if constexpr (COMPA) {
            char* dst = smem + st * STAGE;
            int f0 = (ch << 5) + part * 8;
            float qr[8];
#pragma unroll
            for (int n = 0; n < 8; n++) qr[n] = qsh[rb * 8 + n];
            __half2 hp[4];
#pragma unroll
            for (int jj = 0; jj < 4; jj++) {
                float hv[2];
#pragma unroll
                for (int u = 0; u < 2; u++) {
                    int f = f0 + jj * 2 + u;
                    float h = b1s[f];
#pragma unroll
                    for (int n = 0; n < 8; n++) h += qr[n] * w1s[n * 512 + f];
                    hv[u] = fmaxf(h, 0.f);
                }
                hp[jj] = __halves2half2(__float2half_rn(hv[0]),
                                        __float2half_rn(hv[1]));
            }
            *(uint4*)(dst + rb * 64 + swc) = *(uint4*)hp;
        }
    };

    load_stage(0, 0); comp_h(0, 0);
    load_stage(1, 1); comp_h(1, 1);

    uint32_t rowA = wm * 32 + (lane & 15);
    uint32_t rxA  = (rowA >> 1) & 3;
    uint32_t cA   = (uint32_t)lane >> 4;
    uint32_t rowB = wn * 64 + ((lane >> 4) & 1) * 8 + (lane & 7);
    uint32_t rxB  = (rowB >> 1) & 3;
    uint32_t cB   = ((uint32_t)lane >> 3) & 1;

    int st = 0;
    for (int cc = 0; cc < CH; cc++) {
        if (cc + 1 < CH) cp_wait1(); else cp_wait0();
        __syncthreads();
        if (cc + 2 < CH) {
            int st2 = st + 2; if (st2 >= 3) st2 -= 3;
            load_stage(st2, cc + 2);
            comp_h(st2, cc + 2);
        }
        uint32_t stg = sb + st * STAGE;
        uint32_t aB  = stg + rowA * 64;
        uint32_t bB  = stg + W_O + rowB * 64;

#pragma unroll
        for (int kb = 0; kb < 2; kb++) {
            uint32_t colA = (((uint32_t)(kb * 2) + cA) ^ rxA) << 4;
            uint32_t colB = (((uint32_t)(kb * 2) + cB) ^ rxB) << 4;
            uint32_t b[16];
#pragma unroll
            for (int n2 = 0; n2 < 4; n2++)
                ldm_x4(b[n2*4], b[n2*4+1], b[n2*4+2], b[n2*4+3],
                       bB + n2 * 1024 + colB);
            uint32_t h0[2], h1[2], h2[2], h3[2];
#pragma unroll
            for (int mi = 0; mi < 2; mi++)
                ldm_x4(h0[mi], h1[mi], h2[mi], h3[mi], aB + mi * 1024 + colA);
#pragma unroll
            for (int mi = 0; mi < 2; mi++)
#pragma unroll
                for (int n2 = 0; n2 < 4; n2++) {
                    mma16816(acc[mi][n2*2],   h0[mi], h1[mi], h2[mi], h3[mi],
                             b[n2*4],   b[n2*4+1]);
                    mma16816(acc[mi][n2*2+1], h0[mi], h1[mi], h2[mi], h3[mi],
                             b[n2*4+2], b[n2*4+3]);
                }
            if constexpr (TERMS == 2) {
#pragma unroll
                for (int mi = 0; mi < 2; mi++)
                    ldm_x4(h0[mi], h1[mi], h2[mi], h3[mi],
                           aB + A_LO + mi * 1024 + colA);
#pragma unroll
                for (int mi = 0; mi < 2; mi++)
#pragma unroll
                    for (int n2 = 0; n2 < 4; n2++) {
                        mma16816(acc[mi][n2*2],   h0[mi], h1[mi], h2[mi], h3[mi],
                                 b[n2*4],   b[n2*4+1]);
                        mma16816(acc[mi][n2*2+1], h0[mi], h1[mi], h2[mi], h3[mi],
                                 b[n2*4+2], b[n2*4+3]);
                    }
            }
        }
        if (++st == 3) st = 0;
    }
    __syncthreads();   // all reads of stage buffers done before caller reuses smem
}

// ---------------- epilogue: residual + LN (+ producer) -----------------------
// PROD 0: write g_x + q->qsh.  PROD 1: write g_x + next-layer A hi/lo.
// PROD 2: pool partials only.
template <int PROD>
__device__ __forceinline__ void epilogue(
    float (&acc)[2][8][4], char* smem, size_t bm,
    const float* __restrict__ bias,
    const float* __restrict__ lnG, const float* __restrict__ lnB,
    const float* __restrict__ fTh, const float* __restrict__ thN) {
    float2* red = (float2*)(smem + RED_O);
    float2* mr  = (float2*)(smem + MR_O);
    float*  qsh = (float*)(smem + QSH_O);
    float*  pps = (float*)(smem + PPS_O);
    int tid = threadIdx.x, lane = tid & 31, wid = tid >> 5;
    int wm = wid >> 2, wn = wid & 3;
    int mcol = wn * 64 + (lane & 3) * 2;
    int r0l  = wm * 32 + (lane >> 2);

#pragma unroll
    for (int mi = 0; mi < 2; mi++) {
        float s0 = 0, q0 = 0, s1 = 0, q1 = 0;
        size_t ra = bm + r0l + mi * 16;
#pragma unroll
        for (int ni = 0; ni < 8; ni++) {
            int col = mcol + ni * 8;
            float2 x0 = *(const float2*)(g_x + ra * E_ + col);
            float2 x1 = *(const float2*)(g_x + (ra + 8) * E_ + col);
            float bcx = bias[col], bcy = bias[col + 1];
            float v0 = acc[mi][ni][0] + bcx + x0.x;
            float v1 = acc[mi][ni][1] + bcy + x0.y;
            float v2 = acc[mi][ni][2] + bcx + x1.x;
            float v3 = acc[mi][ni][3] + bcy + x1.y;
            acc[mi][ni][0] = v0; acc[mi][ni][1] = v1;
            acc[mi][ni][2] = v2; acc[mi][ni][3] = v3;
            s0 += v0 + v1; q0 += v0 * v0 + v1 * v1;
            s1 += v2 + v3; q1 += v2 * v2 + v3 * v3;
        }
#pragma unroll
        for (int o = 1; o <= 2; o <<= 1) {
            s0 += __shfl_xor_sync(0xffffffffu, s0, o);
            q0 += __shfl_xor_sync(0xffffffffu, q0, o);
            s1 += __shfl_xor_sync(0xffffffffu, s1, o);
            q1 += __shfl_xor_sync(0xffffffffu, q1, o);
        }
        if ((lane & 3) == 0) {
            int rl = r0l + mi * 16;
            red[rl * 4 + wn] = make_float2(s0, q0);
            red[(rl + 8) * 4 + wn] = make_float2(s1, q1);
        }
    }
    __syncthreads();
    if (tid < 64) {
        float s = 0, q = 0;
#pragma unroll
        for (int j = 0; j < 4; j++) { float2 t = red[tid * 4 + j]; s += t.x; q += t.y; }
        float mean = s * (1.0f / E_);
        float var  = q * (1.0f / E_) - mean * mean;
        mr[tid] = make_float2(mean, rsqrtf(var + 1e-5f));
    }
    __syncthreads();

    float cf0 = 0.f, cf1 = 0.f;
    if constexpr (PROD == 0) {
        int c = (lane & 3) * 2;
        cf0 = cosf(fTh[c]); cf1 = cosf(fTh[c + 1]);
    }
    float ps[8][2];
    if constexpr (PROD == 2) {
#pragma unroll
        for (int ni = 0; ni < 8; ni++) { ps[ni][0] = 0.f; ps[ni][1] = 0.f; }
    }

#pragma unroll
    for (int mi = 0; mi < 2; mi++) {
        int rl = r0l + mi * 16;
        float2 m0 = mr[rl], m1 = mr[rl + 8];
        size_t ra = bm + rl;
#pragma unroll
        for (int ni = 0; ni < 8; ni++) {
            int col = mcol + ni * 8;
            float gx = lnG[col], gy = lnG[col + 1];
            float bx = lnB[col], by = lnB[col + 1];
            float o0 = (acc[mi][ni][0] - m0.x) * m0.y * gx + bx;
            float o1 = (acc[mi][ni][1] - m0.x) * m0.y * gy + by;
            float o2 = (acc[mi][ni][2] - m1.x) * m1.y * gx + bx;
            float o3 = (acc[mi][ni][3] - m1.x) * m1.y * gy + by;
            if constexpr (PROD != 2) {
                *(float2*)(g_x + ra * E_ + col) = make_float2(o0, o1);
                *(float2*)(g_x + (ra + 8) * E_ + col) = make_float2(o2, o3);
            }
            if constexpr (PROD == 0) {
                if (wn == 0 && ni == 0) {
                    int c = (lane & 3) * 2;
                    qsh[rl * 8 + c]           = cosf(o0) * cf0;
                    qsh[rl * 8 + c + 1]       = cosf(o1) * cf1;
                    qsh[(rl + 8) * 8 + c]     = cosf(o2) * cf0;
                    qsh[(rl + 8) * 8 + c + 1] = cosf(o3) * cf1;
                }
            }
            if constexpr (PROD == 1) {
                float t0 = thN[col & 63], t1 = thN[(col + 1) & 63];
                float a0 = cosf(o0 + t0), a1 = cosf(o1 + t1);
                float a2 = cosf(o2 + t0), a3 = cosf(o3 + t1);
                __half p0 = __float2half_rn(a0), p1 = __float2half_rn(a1);
                __half p2 = __float2half_rn(a2), p3 = __float2half_rn(a3);
                *(__half2*)(g_ahi + ra * E_ + col) = __halves2half2(p0, p1);
                *(__half2*)(g_ahi + (ra + 8) * E_ + col) = __halves2half2(p2, p3);
                *(__half2*)(g_alo + ra * E_ + col) =
                    __halves2half2(__float2half_rn(a0 - __half2float(p0)),
                                   __float2half_rn(a1 - __half2float(p1)));
                *(__half2*)(g_alo + (ra + 8) * E_ + col) =
                    __halves2half2(__float2half_rn(a2 - __half2float(p2)),
                                   __float2half_rn(a3 - __half2float(p3)));
            }
            if constexpr (PROD == 2) {
                ps[ni][0] += o0 + o2;
                ps[ni][1] += o1 + o3;
            }
        }
    }

    if constexpr (PROD == 2) {
#pragma unroll
        for (int ni = 0; ni < 8; ni++)
#pragma unroll
            for (int o = 4; o <= 16; o <<= 1) {
                ps[ni][0] += __shfl_xor_sync(0xffffffffu, ps[ni][0], o);
                ps[ni][1] += __shfl_xor_sync(0xffffffffu, ps[ni][1], o);
            }
        if (lane < 4) {
#pragma unroll
            for (int ni = 0; ni < 8; ni++) {
                pps[wm * 256 + mcol + ni * 8]     = ps[ni][0];
                pps[wm * 256 + mcol + ni * 8 + 1] = ps[ni][1];
            }
        }
        __syncthreads();
        if (tid < 256) g_pp[blockIdx.x * 256 + tid] = pps[tid] + pps[256 + tid];
    }
}

// ---------------- fused transformer layer: attn GEMM -> LN1 -> ffn -> LN2 ----
template <int LAYER>
__global__ void __launch_bounds__(256, 2)
k_layer(const __half* __restrict__ Agh, const __half* __restrict__ Agl,
        const __half* __restrict__ Wa, const __half* __restrict__ Wf,
        const float* __restrict__ cb,
        const float* __restrict__ ln1g, const float* __restrict__ ln1b,
        const float* __restrict__ fTh,
        const float* __restrict__ W1, const float* __restrict__ b1,
        const float* __restrict__ l2b,
        const float* __restrict__ ln2g, const float* __restrict__ ln2b,
        const float* __restrict__ thN) {
    extern __shared__ __align__(16) char smem[];
    uint32_t sb = s2u(smem);
    int tid = threadIdx.x;
    size_t bm = (size_t)blockIdx.x * 64;

    float* w1s = (float*)(smem + W1S_O);
    float* b1s = (float*)(smem + B1S_O);
    float* qsh = (float*)(smem + QSH_O);

    // stage W1 ([n][f] layout, same as global) + b1 — consumed in phase B
#pragma unroll
    for (int i = 0; i < 16; i++) w1s[tid + i * 256] = W1[tid + i * 256];
    b1s[tid]       = b1[tid];
    b1s[tid + 256] = b1[tid + 256];

    float acc[2][8][4];
#pragma unroll
    for (int i = 0; i < 2; i++)
#pragma unroll
        for (int j = 0; j < 8; j++)
#pragma unroll
            for (int c = 0; c < 4; c++) acc[i][j][c] = 0.f;

    // phase A: attn GEMM (2-term, K=256)
    run_gemm<256, 2, false>(acc, smem, sb, bm, Agh, Agl, Wa,
                            nullptr, nullptr, nullptr);
    epilogue<0>(acc, smem, bm, cb, ln1g, ln1b, fTh, nullptr);
    __syncthreads();   // qsh ready for comp_h

    // phase B: ffn GEMM (1-term, K=512, A computed in-CTA)
#pragma unroll
    for (int i = 0; i < 2; i++)
#pragma unroll
        for (int j = 0; j < 8; j++)
#pragma unroll
            for (int c = 0; c < 4; c++) acc[i][j][c] = 0.f;
    run_gemm<512, 1, true>(acc, smem, sb, bm, nullptr, nullptr, Wf,
                           qsh, w1s, b1s);
    if constexpr (LAYER == 0)
        epilogue<1>(acc, smem, bm, l2b, ln2g, ln2b, nullptr, thN);
    else
        epilogue<2>(acc, smem, bm, l2b, ln2g, ln2b, nullptr, nullptr);
}

// ---------------- classifier -------------------------------------------------
__global__ void k_cls(const float* __restrict__ w, const float* __restrict__ cb,
                      float* __restrict__ out) {
    __shared__ float sh[16];
    int b = blockIdx.x, e = threadIdx.x;
    float p = 0.f;
#pragma unroll 8
    for (int j = 0; j < 32; j++) p += g_pp[(b * 32 + j) * E_ + e];
    p *= (1.0f / (float)S_);
    float s0 = p * w[e * 2], s1 = p * w[e * 2 + 1];
    for (int o = 16; o > 0; o >>= 1) {
        s0 += __shfl_xor_sync(0xffffffffu, s0, o);
        s1 += __shfl_xor_sync(0xffffffffu, s1, o);
    }
    int wi = e >> 5;
    if ((e & 31) == 0) { sh[wi * 2] = s0; sh[wi * 2 + 1] = s1; }
    __syncthreads();
    if (e == 0) {
        float t0 = 0, t1 = 0;
#pragma unroll
        for (int j = 0; j < 8; j++) { t0 += sh[j * 2]; t1 += sh[j * 2 + 1]; }
        out[b * 2]     = t0 + cb[0];
        out[b * 2 + 1] = t1 + cb[1];
    }
}

// ---------------- host launcher ----------------------------------------------
extern "C" void kernel_launch(void* const* d_in, const int* in_sizes, int n_in,
                              void* d_out, int out_size) {
    const int*   tokens     = (const int*)d_in[0];
    const float* embed      = (const float*)d_in[1];
    const float* attn_theta = (const float*)d_in[2];
    const float* combine_w  = (const float*)d_in[3];
    const float* combine_b  = (const float*)d_in[4];
    const float* ffn_theta  = (const float*)d_in[5];
    const float* lin1_w     = (const float*)d_in[6];
    const float* lin1_b     = (const float*)d_in[7];
    const float* lin2_w     = (const float*)d_in[8];
    const float* lin2_b     = (const float*)d_in[9];
    const float* ln1_g      = (const float*)d_in[10];
    const float* ln1_b      = (const float*)d_in[11];
    const float* ln2_g      = (const float*)d_in[12];
    const float* ln2_b      = (const float*)d_in[13];
    const float* cls_w      = (const float*)d_in[14];
    const float* cls_b      = (const float*)d_in[15];
    float* out = (float*)d_out;

    __half *ahi, *alo, *wh;
    cudaGetSymbolAddress((void**)&ahi, g_ahi);
    cudaGetSymbolAddress((void**)&alo, g_alo);
    cudaGetSymbolAddress((void**)&wh,  g_wh);

    cudaFuncSetAttribute(k_layer<0>, cudaFuncAttributeMaxDynamicSharedMemorySize, SME_T);
    cudaFuncSetAttribute(k_layer<1>, cudaFuncAttributeMaxDynamicSharedMemorySize, SME_T);

    k_embed<<<M_, 256>>>(tokens, embed, attn_theta);
    k_convw<<<dim3(256, 4), 256>>>(combine_w, lin2_w);

    k_layer<0><<<M_ / 64, 256, SME_T>>>(
        ahi, alo, wh + 0 * 131072, wh + 2 * 131072,
        combine_b, ln1_g, ln1_b,
        ffn_theta, lin1_w, lin1_b,
        lin2_b, ln2_g, ln2_b, attn_theta + 64);
    k_layer<1><<<M_ / 64, 256, SME_T>>>(
        ahi, alo, wh + 1 * 131072, wh + 3 * 131072,
        combine_b + E_, ln1_g + E_, ln1_b + E_,
        ffn_theta + NQ_, lin1_w + NQ_ * FFN_, lin1_b + FFN_,
        lin2_b + E_, ln2_g + E_, ln2_b + E_, nullptr);

    k_cls<<<B_, 256>>>(cls_w, cls_b, out);
}

// round 13
// speedup vs baseline: 1.2749x; 1.0806x over previous
#include <cuda_runtime.h>
#include <cuda_fp16.h>
#include <cstdint>
#include <math.h>

#define B_   16
#define S_   2048
#define E_   256
#define L_   2
#define NQ_  8
#define FFN_ 512
#define C_   2
#define M_   (B_*S_)   // 32768 rows

// ---------------- scratch (__device__ globals; no allocations) ---------------
__device__ float g_x[(size_t)M_*E_];                      // 32 MB
__device__ __align__(128) __half g_ah[(size_t)M_*E_];     // 16 MB  attn A (fp16)
__device__ __align__(128) __half g_wh[4*256*512];         // Wt[n][k] fp16
__device__ float g_pp[512*E_];                            // pool partials

// ---------------- smem layout (bytes) ----------------------------------------
// stages: [0, 61440)  (3 x 20480, both phases)
#define W1S_O  61440    // [8][512] float, [n][f] layout, 16384 B
#define B1S_O  77824    // [512] float, 2048 B
#define QSH_O  79872    // [64][8] float, 2048 B
#define RED_O  81920    // [64][4] float2, 2048 B
#define MR_O   83968    // [64] float2, 512 B
#define PPS_O  84480    // [2][256] float, 2048 B
#define SME_T  86528

// ---------------- PTX helpers ------------------------------------------------
__device__ __forceinline__ uint32_t s2u(const void* p) {
    uint32_t a;
    asm("{ .reg .u64 t; cvta.to.shared.u64 t, %1; cvt.u32.u64 %0, t; }"
        : "=r"(a) : "l"(p));
    return a;
}
__device__ __forceinline__ void cp16(uint32_t dst, const void* src) {
    asm volatile("cp.async.cg.shared.global [%0], [%1], 16;" :: "r"(dst), "l"(src));
}
__device__ __forceinline__ void cp_commit() {
    asm volatile("cp.async.commit_group;" ::: "memory");
}
__device__ __forceinline__ void cp_wait1() {
    asm volatile("cp.async.wait_group 1;" ::: "memory");
}
__device__ __forceinline__ void cp_wait0() {
    asm volatile("cp.async.wait_group 0;" ::: "memory");
}
__device__ __forceinline__ void ldm_x4(uint32_t& r0, uint32_t& r1, uint32_t& r2,
                                       uint32_t& r3, uint32_t addr) {
    asm volatile("ldmatrix.sync.aligned.m8n8.x4.shared.b16 {%0,%1,%2,%3}, [%4];"
                 : "=r"(r0), "=r"(r1), "=r"(r2), "=r"(r3) : "r"(addr));
}
__device__ __forceinline__ void mma16816(float* c, uint32_t a0, uint32_t a1,
                                         uint32_t a2, uint32_t a3,
                                         uint32_t b0, uint32_t b1) {
    asm volatile(
        "mma.sync.aligned.m16n8k16.row.col.f32.f16.f16.f32 "
        "{%0,%1,%2,%3}, {%4,%5,%6,%7}, {%8,%9}, {%0,%1,%2,%3};"
        : "+f"(c[0]), "+f"(c[1]), "+f"(c[2]), "+f"(c[3])
        : "r"(a0), "r"(a1), "r"(a2), "r"(a3), "r"(b0), "r"(b1));
}

// ---------------- embed + PE + fused prep for layer-0 attn -------------------
__global__ void k_embed(const int* __restrict__ tok, const float* __restrict__ emb,
                        const float* __restrict__ th) {
    int row = blockIdx.x;
    int e   = threadIdx.x;
    int t   = tok[row];
    int s   = row & (S_ - 1);
    int i   = e >> 1;
    float freq = expf(-(float)(2 * i) * (9.210340371976184f / (float)E_));
    float ang  = (float)s * freq;
    float pe   = (e & 1) ? cosf(ang) : sinf(ang);
    size_t idx = (size_t)row * E_ + e;
    float x = emb[(size_t)t * E_ + e] + pe;
    g_x[idx] = x;
    g_ah[idx] = __float2half_rn(cosf(x + th[e & 63]));
}

// ---------------- weight convert + transpose (fp16) --------------------------
__global__ void k_convw(const float* __restrict__ cw, const float* __restrict__ l2w) {
    int slot = blockIdx.y;
    int n    = blockIdx.x;
    int K    = (slot < 2) ? 256 : 512;
    const float* src = (slot < 2) ? (cw + (size_t)slot * E_ * E_)
                                  : (l2w + (size_t)(slot - 2) * FFN_ * E_);
    for (int k = threadIdx.x; k < K; k += 256) {
        float w = src[(size_t)k * E_ + n];
        g_wh[(size_t)slot * 131072 + (size_t)n * K + k] = __float2half_rn(w);
    }
}

// ---------------- GEMM phase: BM=64, BN=256, BK=32, 256 thr (2Mx4N warps) ----
// Single fp16 term: D += A*W. COMPA: A chunk computed from q @ W1 + b1 (relu,
// fp16) in-CTA. 64B smem rows, XOR-4 swizzle. 3-stage pipeline, 1 barrier/chunk.
template <int K, bool COMPA>
__device__ __forceinline__ void run_gemm(
    float (&acc)[2][8][4], char* smem, uint32_t sb, size_t bm,
    const __half* __restrict__ Ag, const __half* __restrict__ W,
    const float* qsh, const float* w1s, const float* b1s) {
    constexpr int CH    = K >> 5;
    constexpr int W_O   = 4096;
    constexpr int STAGE = 20480;
    int tid = threadIdx.x, lane = tid & 31, wid = tid >> 5;
    int wm = wid >> 2, wn = wid & 3;
    int part = tid & 3, rb = tid >> 2;                    // rb 0..63
    uint32_t swc = (uint32_t)(part ^ ((rb >> 1) & 3)) << 4;

    auto load_stage = [&](int st, int ch) {
        uint32_t dst = sb + st * STAGE;
        int kk = ch << 5;
        if constexpr (!COMPA)
            cp16(dst + rb * 64 + swc, Ag + (bm + rb) * (size_t)K + kk + part * 8);
#pragma unroll
        for (int i = 0; i < 4; i++) {
            int r = rb + i * 64;
            cp16(dst + W_O + r * 64 + swc, W + (size_t)r * K + kk + part * 8);
        }
        cp_commit();
    };

    auto comp_h = [&](int st, int ch) {
        if constexpr (COMPA) {
            char* dst = smem + st * STAGE;
            int f0 = (ch << 5) + part * 8;
            float qr[8];
#pragma unroll
            for (int n = 0; n < 8; n++) qr[n] = qsh[rb * 8 + n];
            __half2 hp[4];
#pragma unroll
            for (int jj = 0; jj < 4; jj++) {
                float hv[2];
#pragma unroll
                for (int u = 0; u < 2; u++) {
                    int f = f0 + jj * 2 + u;
                    float h = b1s[f];
#pragma unroll
                    for (int n = 0; n < 8; n++) h += qr[n] * w1s[n * 512 + f];
                    hv[u] = fmaxf(h, 0.f);
                }
                hp[jj] = __halves2half2(__float2half_rn(hv[0]),
                                        __float2half_rn(hv[1]));
            }
            *(uint4*)(dst + rb * 64 + swc) = *(uint4*)hp;
        }
    };

    load_stage(0, 0); comp_h(0, 0);
    load_stage(1, 1); comp_h(1, 1);

    uint32_t rowA = wm * 32 + (lane & 15);
    uint32_t rxA  = (rowA >> 1) & 3;
    uint32_t cA   = (uint32_t)lane >> 4;
    uint32_t rowB = wn * 64 + ((lane >> 4) & 1) * 8 + (lane & 7);
    uint32_t rxB  = (rowB >> 1) & 3;
    uint32_t cB   = ((uint32_t)lane >> 3) & 1;

    int st = 0;
    for (int cc = 0; cc < CH; cc++) {
        if (cc + 1 < CH) cp_wait1(); else cp_wait0();
        __syncthreads();
        if (cc + 2 < CH) {
            int st2 = st + 2; if (st2 >= 3) st2 -= 3;
            load_stage(st2, cc + 2);
            comp_h(st2, cc + 2);
        }
        uint32_t stg = sb + st * STAGE;
        uint32_t aB  = stg + rowA * 64;
        uint32_t bB  = stg + W_O + rowB * 64;

#pragma unroll
        for (int kb = 0; kb < 2; kb++) {
            uint32_t colA = (((uint32_t)(kb * 2) + cA) ^ rxA) << 4;
            uint32_t colB = (((uint32_t)(kb * 2) + cB) ^ rxB) << 4;
            uint32_t b[16];
#pragma unroll
            for (int n2 = 0; n2 < 4; n2++)
                ldm_x4(b[n2*4], b[n2*4+1], b[n2*4+2], b[n2*4+3],
                       bB + n2 * 1024 + colB);
            uint32_t h0[2], h1[2], h2[2], h3[2];
#pragma unroll
            for (int mi = 0; mi < 2; mi++)
                ldm_x4(h0[mi], h1[mi], h2[mi], h3[mi], aB + mi * 1024 + colA);
#pragma unroll
            for (int mi = 0; mi < 2; mi++)
#pragma unroll
                for (int n2 = 0; n2 < 4; n2++) {
                    mma16816(acc[mi][n2*2],   h0[mi], h1[mi], h2[mi], h3[mi],
                             b[n2*4],   b[n2*4+1]);
                    mma16816(acc[mi][n2*2+1], h0[mi], h1[mi], h2[mi], h3[mi],
                             b[n2*4+2], b[n2*4+3]);
                }
        }
        if (++st == 3) st = 0;
    }
    __syncthreads();   // all stage-buffer reads done before caller reuses smem
}

// ---------------- epilogue: residual + LN (+ producer) -----------------------
// PROD 0: write g_x + q->qsh.  PROD 1: write g_x + next-layer A (fp16).
// PROD 2: pool partials only.
template <int PROD>
__device__ __forceinline__ void epilogue(
    float (&acc)[2][8][4], char* smem, size_t bm,
    const float* __restrict__ bias,
    const float* __restrict__ lnG, const float* __restrict__ lnB,
    const float* __restrict__ fTh, const float* __restrict__ thN) {
    float2* red = (float2*)(smem + RED_O);
    float2* mr  = (float2*)(smem + MR_O);
    float*  qsh = (float*)(smem + QSH_O);
    float*  pps = (float*)(smem + PPS_O);
    int tid = threadIdx.x, lane = tid & 31, wid = tid >> 5;
    int wm = wid >> 2, wn = wid & 3;
    int mcol = wn * 64 + (lane & 3) * 2;
    int r0l  = wm * 32 + (lane >> 2);

#pragma unroll
    for (int mi = 0; mi < 2; mi++) {
        float s0 = 0, q0 = 0, s1 = 0, q1 = 0;
        size_t ra = bm + r0l + mi * 16;
#pragma unroll
        for (int ni = 0; ni < 8; ni++) {
            int col = mcol + ni * 8;
            float2 x0 = *(const float2*)(g_x + ra * E_ + col);
            float2 x1 = *(const float2*)(g_x + (ra + 8) * E_ + col);
            float bcx = bias[col], bcy = bias[col + 1];
            float v0 = acc[mi][ni][0] + bcx + x0.x;
            float v1 = acc[mi][ni][1] + bcy + x0.y;
            float v2 = acc[mi][ni][2] + bcx + x1.x;
            float v3 = acc[mi][ni][3] + bcy + x1.y;
            acc[mi][ni][0] = v0; acc[mi][ni][1] = v1;
            acc[mi][ni][2] = v2; acc[mi][ni][3] = v3;
            s0 += v0 + v1; q0 += v0 * v0 + v1 * v1;
            s1 += v2 + v3; q1 += v2 * v2 + v3 * v3;
        }
#pragma unroll
        for (int o = 1; o <= 2; o <<= 1) {
            s0 += __shfl_xor_sync(0xffffffffu, s0, o);
            q0 += __shfl_xor_sync(0xffffffffu, q0, o);
            s1 += __shfl_xor_sync(0xffffffffu, s1, o);
            q1 += __shfl_xor_sync(0xffffffffu, q1, o);
        }
        if ((lane & 3) == 0) {
            int rl = r0l + mi * 16;
            red[rl * 4 + wn] = make_float2(s0, q0);
            red[(rl + 8) * 4 + wn] = make_float2(s1, q1);
        }
    }
    __syncthreads();
    if (tid < 64) {
        float s = 0, q = 0;
#pragma unroll
        for (int j = 0; j < 4; j++) { float2 t = red[tid * 4 + j]; s += t.x; q += t.y; }
        float mean = s * (1.0f / E_);
        float var  = q * (1.0f / E_) - mean * mean;
        mr[tid] = make_float2(mean, rsqrtf(var + 1e-5f));
    }
    __syncthreads();

    float cf0 = 0.f, cf1 = 0.f;
    if constexpr (PROD == 0) {
        int c = (lane & 3) * 2;
        cf0 = cosf(fTh[c]); cf1 = cosf(fTh[c + 1]);
    }
    float ps[8][2];
    if constexpr (PROD == 2) {
#pragma unroll
        for (int ni = 0; ni < 8; ni++) { ps[ni][0] = 0.f; ps[ni][1] = 0.f; }
    }

#pragma unroll
    for (int mi = 0; mi < 2; mi++) {
        int rl = r0l + mi * 16;
        float2 m0 = mr[rl], m1 = mr[rl + 8];
        size_t ra = bm + rl;
#pragma unroll
        for (int ni = 0; ni < 8; ni++) {
            int col = mcol + ni * 8;
            float gx = lnG[col], gy = lnG[col + 1];
            float bx = lnB[col], by = lnB[col + 1];
            float o0 = (acc[mi][ni][0] - m0.x) * m0.y * gx + bx;
            float o1 = (acc[mi][ni][1] - m0.x) * m0.y * gy + by;
            float o2 = (acc[mi][ni][2] - m1.x) * m1.y * gx + bx;
            float o3 = (acc[mi][ni][3] - m1.x) * m1.y * gy + by;
            if constexpr (PROD != 2) {
                *(float2*)(g_x + ra * E_ + col) = make_float2(o0, o1);
                *(float2*)(g_x + (ra + 8) * E_ + col) = make_float2(o2, o3);
            }
            if constexpr (PROD == 0) {
                if (wn == 0 && ni == 0) {
                    int c = (lane & 3) * 2;
                    qsh[rl * 8 + c]           = cosf(o0) * cf0;
                    qsh[rl * 8 + c + 1]       = cosf(o1) * cf1;
                    qsh[(rl + 8) * 8 + c]     = cosf(o2) * cf0;
                    qsh[(rl + 8) * 8 + c + 1] = cosf(o3) * cf1;
                }
            }
            if constexpr (PROD == 1) {
                float t0 = thN[col & 63], t1 = thN[(col + 1) & 63];
                *(__half2*)(g_ah + ra * E_ + col) =
                    __halves2half2(__float2half_rn(cosf(o0 + t0)),
                                   __float2half_rn(cosf(o1 + t1)));
                *(__half2*)(g_ah + (ra + 8) * E_ + col) =
                    __halves2half2(__float2half_rn(cosf(o2 + t0)),
                                   __float2half_rn(cosf(o3 + t1)));
            }
            if constexpr (PROD == 2) {
                ps[ni][0] += o0 + o2;
                ps[ni][1] += o1 + o3;
            }
        }
    }

    if constexpr (PROD == 2) {
#pragma unroll
        for (int ni = 0; ni < 8; ni++)
#pragma unroll
            for (int o = 4; o <= 16; o <<= 1) {
                ps[ni][0] += __shfl_xor_sync(0xffffffffu, ps[ni][0], o);
                ps[ni][1] += __shfl_xor_sync(0xffffffffu, ps[ni][1], o);
            }
        if (lane < 4) {
#pragma unroll
            for (int ni = 0; ni < 8; ni++) {
                pps[wm * 256 + mcol + ni * 8]     = ps[ni][0];
                pps[wm * 256 + mcol + ni * 8 + 1] = ps[ni][1];
            }
        }
        __syncthreads();
        if (tid < 256) g_pp[blockIdx.x * 256 + tid] = pps[tid] + pps[256 + tid];
    }
}

// ---------------- fused transformer layer: attn GEMM -> LN1 -> ffn -> LN2 ----
template <int LAYER>
__global__ void __launch_bounds__(256, 2)
k_layer(const __half* __restrict__ Ag,
        const __half* __restrict__ Wa, const __half* __restrict__ Wf,
        const float* __restrict__ cb,
        const float* __restrict__ ln1g, const float* __restrict__ ln1b,
        const float* __restrict__ fTh,
        const float* __restrict__ W1, const float* __restrict__ b1,
        const float* __restrict__ l2b,
        const float* __restrict__ ln2g, const float* __restrict__ ln2b,
        const float* __restrict__ thN) {
    extern __shared__ __align__(16) char smem[];
    uint32_t sb = s2u(smem);
    int tid = threadIdx.x;
    size_t bm = (size_t)blockIdx.x * 64;

    float* w1s = (float*)(smem + W1S_O);
    float* b1s = (float*)(smem + B1S_O);
    float* qsh = (float*)(smem + QSH_O);

    // stage W1 ([n][f] layout, same as global) + b1 — consumed in phase B
#pragma unroll
    for (int i = 0; i < 16; i++) w1s[tid + i * 256] = W1[tid + i * 256];
    b1s[tid]       = b1[tid];
    b1s[tid + 256] = b1[tid + 256];

    float acc[2][8][4];
#pragma unroll
    for (int i = 0; i < 2; i++)
#pragma unroll
        for (int j = 0; j < 8; j++)
#pragma unroll
            for (int c = 0; c < 4; c++) acc[i][j][c] = 0.f;

    // phase A: attn GEMM (K=256, A from global)
    run_gemm<256, false>(acc, smem, sb, bm, Ag, Wa, nullptr, nullptr, nullptr);
    epilogue<0>(acc, smem, bm, cb, ln1g, ln1b, fTh, nullptr);
    __syncthreads();   // qsh ready for comp_h

    // phase B: ffn GEMM (K=512, A computed in-CTA)
#pragma unroll
    for (int i = 0; i < 2; i++)
#pragma unroll
        for (int j = 0; j < 8; j++)
#pragma unroll
            for (int c = 0; c < 4; c++) acc[i][j][c] = 0.f;
    run_gemm<512, true>(acc, smem, sb, bm, nullptr, Wf, qsh, w1s, b1s);
    if constexpr (LAYER == 0)
        epilogue<1>(acc, smem, bm, l2b, ln2g, ln2b, nullptr, thN);
    else
        epilogue<2>(acc, smem, bm, l2b, ln2g, ln2b, nullptr, nullptr);
}

// ---------------- classifier -------------------------------------------------
__global__ void k_cls(const float* __restrict__ w, const float* __restrict__ cb,
                      float* __restrict__ out) {
    __shared__ float sh[16];
    int b = blockIdx.x, e = threadIdx.x;
    float p = 0.f;
#pragma unroll 8
    for (int j = 0; j < 32; j++) p += g_pp[(b * 32 + j) * E_ + e];
    p *= (1.0f / (float)S_);
    float s0 = p * w[e * 2], s1 = p * w[e * 2 + 1];
    for (int o = 16; o > 0; o >>= 1) {
        s0 += __shfl_xor_sync(0xffffffffu, s0, o);
        s1 += __shfl_xor_sync(0xffffffffu, s1, o);
    }
    int wi = e >> 5;
    if ((e & 31) == 0) { sh[wi * 2] = s0; sh[wi * 2 + 1] = s1; }
    __syncthreads();
    if (e == 0) {
        float t0 = 0, t1 = 0;
#pragma unroll
        for (int j = 0; j < 8; j++) { t0 += sh[j * 2]; t1 += sh[j * 2 + 1]; }
        out[b * 2]     = t0 + cb[0];
        out[b * 2 + 1] = t1 + cb[1];
    }
}

// ---------------- host launcher ----------------------------------------------
extern "C" void kernel_launch(void* const* d_in, const int* in_sizes, int n_in,
                              void* d_out, int out_size) {
    const int*   tokens     = (const int*)d_in[0];
    const float* embed      = (const float*)d_in[1];
    const float* attn_theta = (const float*)d_in[2];
    const float* combine_w  = (const float*)d_in[3];
    const float* combine_b  = (const float*)d_in[4];
    const float* ffn_theta  = (const float*)d_in[5];
    const float* lin1_w     = (const float*)d_in[6];
    const float* lin1_b     = (const float*)d_in[7];
    const float* lin2_w     = (const float*)d_in[8];
    const float* lin2_b     = (const float*)d_in[9];
    const float* ln1_g      = (const float*)d_in[10];
    const float* ln1_b      = (const float*)d_in[11];
    const float* ln2_g      = (const float*)d_in[12];
    const float* ln2_b      = (const float*)d_in[13];
    const float* cls_w      = (const float*)d_in[14];
    const float* cls_b      = (const float*)d_in[15];
    float* out = (float*)d_out;

    __half *ah, *wh;
    cudaGetSymbolAddress((void**)&ah, g_ah);
    cudaGetSymbolAddress((void**)&wh, g_wh);

    cudaFuncSetAttribute(k_layer<0>, cudaFuncAttributeMaxDynamicSharedMemorySize, SME_T);
    cudaFuncSetAttribute(k_layer<1>, cudaFuncAttributeMaxDynamicSharedMemorySize, SME_T);

    k_embed<<<M_, 256>>>(tokens, embed, attn_theta);
    k_convw<<<dim3(256, 4), 256>>>(combine_w, lin2_w);

    k_layer<0><<<M_ / 64, 256, SME_T>>>(
        ah, wh + 0 * 131072, wh + 2 * 131072,
        combine_b, ln1_g, ln1_b,
        ffn_theta, lin1_w, lin1_b,
        lin2_b, ln2_g, ln2_b, attn_theta + 64);
    k_layer<1><<<M_ / 64, 256, SME_T>>>(
        ah, wh + 1 * 131072, wh + 3 * 131072,
        combine_b + E_, ln1_g + E_, ln1_b + E_,
        ffn_theta + NQ_, lin1_w + NQ_ * FFN_, lin1_b + FFN_,
        lin2_b + E_, ln2_g + E_, ln2_b + E_, nullptr);

    k_cls<<<B_, 256>>>(cls_w, cls_b, out);
}

// round 14
// speedup vs baseline: 1.6980x; 1.3319x over previous
#include <cuda_runtime.h>
#include <cuda_fp16.h>
#include <cstdint>
#include <math.h>

#define B_   16
#define S_   2048
#define E_   256
#define L_   2
#define NQ_  8
#define FFN_ 512
#define C_   2
#define M_   (B_*S_)   // 32768 rows

// ---------------- scratch (__device__ globals; no allocations) ---------------
__device__ float g_x[(size_t)M_*E_];                      // 32 MB
__device__ __align__(128) __half g_ah[(size_t)M_*E_];     // 16 MB  attn A (fp16)
__device__ __align__(128) __half g_wh[4*256*512];         // Wt[n][k] fp16
__device__ float g_pp[512*E_];                            // pool partials

// ---------------- smem layout (bytes) ----------------------------------------
// stages: [0, 61440)  (3 x 20480, both phases)
#define W1S_O  61440    // [8][512] float, [n][f] layout, 16384 B
#define B1S_O  77824    // [512] float, 2048 B
#define QSH_O  79872    // [64][8] float, 2048 B
#define RED_O  81920    // [64][4] float2, 2048 B
#define MR_O   83968    // [64] float2, 512 B
#define SME_T  84480

// ---------------- PTX helpers ------------------------------------------------
__device__ __forceinline__ uint32_t s2u(const void* p) {
    uint32_t a;
    asm("{ .reg .u64 t; cvta.to.shared.u64 t, %1; cvt.u32.u64 %0, t; }"
        : "=r"(a) : "l"(p));
    return a;
}
__device__ __forceinline__ void cp16(uint32_t dst, const void* src) {
    asm volatile("cp.async.cg.shared.global [%0], [%1], 16;" :: "r"(dst), "l"(src));
}
__device__ __forceinline__ void cp_commit() {
    asm volatile("cp.async.commit_group;" ::: "memory");
}
__device__ __forceinline__ void cp_wait1() {
    asm volatile("cp.async.wait_group 1;" ::: "memory");
}
__device__ __forceinline__ void cp_wait0() {
    asm volatile("cp.async.wait_group 0;" ::: "memory");
}
__device__ __forceinline__ void ldm_x4(uint32_t& r0, uint32_t& r1, uint32_t& r2,
                                       uint32_t& r3, uint32_t addr) {
    asm volatile("ldmatrix.sync.aligned.m8n8.x4.shared.b16 {%0,%1,%2,%3}, [%4];"
                 : "=r"(r0), "=r"(r1), "=r"(r2), "=r"(r3) : "r"(addr));
}
__device__ __forceinline__ void mma16816(float* c, uint32_t a0, uint32_t a1,
                                         uint32_t a2, uint32_t a3,
                                         uint32_t b0, uint32_t b1) {
    asm volatile(
        "mma.sync.aligned.m16n8k16.row.col.f32.f16.f16.f32 "
        "{%0,%1,%2,%3}, {%4,%5,%6,%7}, {%8,%9}, {%0,%1,%2,%3};"
        : "+f"(c[0]), "+f"(c[1]), "+f"(c[2]), "+f"(c[3])
        : "r"(a0), "r"(a1), "r"(a2), "r"(a3), "r"(b0), "r"(b1));
}

// ---------------- embed + PE + fused prep for layer-0 attn -------------------
__global__ void k_embed(const int* __restrict__ tok, const float* __restrict__ emb,
                        const float* __restrict__ th) {
    int row = blockIdx.x;
    int e   = threadIdx.x;
    int t   = tok[row];
    int s   = row & (S_ - 1);
    int i   = e >> 1;
    float freq = __expf(-(float)(2 * i) * (9.210340371976184f / (float)E_));
    float ang  = (float)s * freq;
    float pe   = (e & 1) ? __cosf(ang) : __sinf(ang);
    size_t idx = (size_t)row * E_ + e;
    float x = emb[(size_t)t * E_ + e] + pe;
    g_x[idx] = x;
    g_ah[idx] = __float2half_rn(__cosf(x + th[e & 63]));
}

// ---------------- weight convert + transpose (fp16) --------------------------
__global__ void k_convw(const float* __restrict__ cw, const float* __restrict__ l2w) {
    int slot = blockIdx.y;
    int n    = blockIdx.x;
    int K    = (slot < 2) ? 256 : 512;
    const float* src = (slot < 2) ? (cw + (size_t)slot * E_ * E_)
                                  : (l2w + (size_t)(slot - 2) * FFN_ * E_);
    for (int k = threadIdx.x; k < K; k += 256) {
        float w = src[(size_t)k * E_ + n];
        g_wh[(size_t)slot * 131072 + (size_t)n * K + k] = __float2half_rn(w);
    }
}

// ---------------- GEMM phase: BM=64, BN=256, BK=32, 128 thr ------------------
// 4 warps, warp tile 64x64 (each warp: all 64 M rows x 64 N cols).
// Per k16: 8 ldmatrix.x4 -> 32 MMAs. 64B rows, XOR-4 swizzle, 3-stage pipeline.
// COMPA: A chunk computed in-CTA from q @ W1 + b1 (relu, fp16).
template <int K, bool COMPA>
__device__ __forceinline__ void run_gemm(
    float (&acc)[4][8][4], char* smem, uint32_t sb, size_t bm,
    const __half* __restrict__ Ag, const __half* __restrict__ W,
    const float* qsh, const float* w1s, const float* b1s) {
    constexpr int CH    = K >> 5;
    constexpr int W_O   = 4096;
    constexpr int STAGE = 20480;
    int tid = threadIdx.x, lane = tid & 31, wn = tid >> 5;

    // loaders: 128 threads
    int part = tid & 3, rb = tid >> 2;                    // rb 0..31
    uint32_t swc = (uint32_t)(part ^ ((rb >> 1) & 3)) << 4;

    auto load_stage = [&](int st, int ch) {
        uint32_t dst = sb + st * STAGE;
        int kk = ch << 5;
        if constexpr (!COMPA) {
#pragma unroll
            for (int i = 0; i < 2; i++) {
                int r = rb + i * 32;
                uint32_t sw = (uint32_t)(part ^ ((r >> 1) & 3)) << 4;
                cp16(dst + r * 64 + sw, Ag + (bm + r) * (size_t)K + kk + part * 8);
            }
        }
#pragma unroll
        for (int i = 0; i < 8; i++) {
            int r = rb + i * 32;
            uint32_t sw = (uint32_t)(part ^ ((r >> 1) & 3)) << 4;
            cp16(dst + W_O + r * 64 + sw, W + (size_t)r * K + kk + part * 8);
        }
        cp_commit();
        (void)swc;
    };

    auto comp_h = [&](int st, int ch) {
        if constexpr (COMPA) {
            char* dst = smem + st * STAGE;
            int r = tid >> 1, half = tid & 1;             // r 0..63
            int f0 = (ch << 5) + half * 16;
            float qr[8];
#pragma unroll
            for (int n = 0; n < 8; n++) qr[n] = qsh[r * 8 + n];
            __half2 hp[8];
#pragma unroll
            for (int jj = 0; jj < 8; jj++) {
                float hv[2];
#pragma unroll
                for (int u = 0; u < 2; u++) {
                    int f = f0 + jj * 2 + u;
                    float h = b1s[f];
#pragma unroll
                    for (int n = 0; n < 8; n++) h += qr[n] * w1s[n * 512 + f];
                    hv[u] = fmaxf(h, 0.f);
                }
                hp[jj] = __halves2half2(__float2half_rn(hv[0]),
                                        __float2half_rn(hv[1]));
            }
            uint32_t swz = (uint32_t)((r >> 1) & 3);
            uint32_t o0 = (uint32_t)r * 64 + (((uint32_t)(half * 2)     ^ swz) << 4);
            uint32_t o1 = (uint32_t)r * 64 + (((uint32_t)(half * 2 + 1) ^ swz) << 4);
            *(uint4*)(dst + o0) = *(uint4*)&hp[0];
            *(uint4*)(dst + o1) = *(uint4*)&hp[4];
        }
    };

    load_stage(0, 0); comp_h(0, 0);
    load_stage(1, 1); comp_h(1, 1);

    uint32_t rowA = lane & 15;                            // + mi*16 (mi*16>>1 %4 == 0)
    uint32_t rxA  = (rowA >> 1) & 3;
    uint32_t cA   = (uint32_t)lane >> 4;                  // 0..1
    uint32_t rowB = wn * 64 + ((lane >> 4) & 1) * 8 + (lane & 7);  // + n2*16
    uint32_t rxB  = (rowB >> 1) & 3;
    uint32_t cB   = ((uint32_t)lane >> 3) & 1;

    int st = 0;
    for (int cc = 0; cc < CH; cc++) {
        if (cc + 1 < CH) cp_wait1(); else cp_wait0();
        __syncthreads();
        if (cc + 2 < CH) {
            int st2 = st + 2; if (st2 >= 3) st2 -= 3;
            load_stage(st2, cc + 2);
            comp_h(st2, cc + 2);
        }
        uint32_t stg = sb + st * STAGE;
        uint32_t aB  = stg + rowA * 64;
        uint32_t bB  = stg + W_O + rowB * 64;

#pragma unroll
        for (int kb = 0; kb < 2; kb++) {
            uint32_t colA = (((uint32_t)(kb * 2) + cA) ^ rxA) << 4;
            uint32_t colB = (((uint32_t)(kb * 2) + cB) ^ rxB) << 4;
            uint32_t b[16];
#pragma unroll
            for (int n2 = 0; n2 < 4; n2++)
                ldm_x4(b[n2*4], b[n2*4+1], b[n2*4+2], b[n2*4+3],
                       bB + n2 * 1024 + colB);
            uint32_t a0[4], a1[4], a2[4], a3[4];
#pragma unroll
            for (int mi = 0; mi < 4; mi++)
                ldm_x4(a0[mi], a1[mi], a2[mi], a3[mi], aB + mi * 1024 + colA);
#pragma unroll
            for (int mi = 0; mi < 4; mi++)
#pragma unroll
                for (int n2 = 0; n2 < 4; n2++) {
                    mma16816(acc[mi][n2*2],   a0[mi], a1[mi], a2[mi], a3[mi],
                             b[n2*4],   b[n2*4+1]);
                    mma16816(acc[mi][n2*2+1], a0[mi], a1[mi], a2[mi], a3[mi],
                             b[n2*4+2], b[n2*4+3]);
                }
        }
        if (++st == 3) st = 0;
    }
    __syncthreads();   // all stage-buffer reads done before caller reuses smem
}

// ---------------- epilogue: residual + LN (+ producer) -----------------------
// PROD 0: write g_x + q->qsh.  PROD 1: write g_x + next-layer A (fp16).
// PROD 2: pool partials only.
template <int PROD>
__device__ __forceinline__ void epilogue(
    float (&acc)[4][8][4], char* smem, size_t bm,
    const float* __restrict__ bias,
    const float* __restrict__ lnG, const float* __restrict__ lnB,
    const float* __restrict__ fTh, const float* __restrict__ thN) {
    float2* red = (float2*)(smem + RED_O);
    float2* mr  = (float2*)(smem + MR_O);
    float*  qsh = (float*)(smem + QSH_O);
    int tid = threadIdx.x, lane = tid & 31, wn = tid >> 5;
    int mcol = wn * 64 + (lane & 3) * 2;
    int r0l  = lane >> 2;                                 // 0..7

#pragma unroll
    for (int mi = 0; mi < 4; mi++) {
        float s0 = 0, q0 = 0, s1 = 0, q1 = 0;
        size_t ra = bm + r0l + mi * 16;
#pragma unroll
        for (int ni = 0; ni < 8; ni++) {
            int col = mcol + ni * 8;
            float2 x0 = *(const float2*)(g_x + ra * E_ + col);
            float2 x1 = *(const float2*)(g_x + (ra + 8) * E_ + col);
            float bcx = bias[col], bcy = bias[col + 1];
            float v0 = acc[mi][ni][0] + bcx + x0.x;
            float v1 = acc[mi][ni][1] + bcy + x0.y;
            float v2 = acc[mi][ni][2] + bcx + x1.x;
            float v3 = acc[mi][ni][3] + bcy + x1.y;
            acc[mi][ni][0] = v0; acc[mi][ni][1] = v1;
            acc[mi][ni][2] = v2; acc[mi][ni][3] = v3;
            s0 += v0 + v1; q0 += v0 * v0 + v1 * v1;
            s1 += v2 + v3; q1 += v2 * v2 + v3 * v3;
        }
#pragma unroll
        for (int o = 1; o <= 2; o <<= 1) {
            s0 += __shfl_xor_sync(0xffffffffu, s0, o);
            q0 += __shfl_xor_sync(0xffffffffu, q0, o);
            s1 += __shfl_xor_sync(0xffffffffu, s1, o);
            q1 += __shfl_xor_sync(0xffffffffu, q1, o);
        }
        if ((lane & 3) == 0) {
            int rl = r0l + mi * 16;
            red[rl * 4 + wn] = make_float2(s0, q0);
            red[(rl + 8) * 4 + wn] = make_float2(s1, q1);
        }
    }
    __syncthreads();
    if (tid < 64) {
        float s = 0, q = 0;
#pragma unroll
        for (int j = 0; j < 4; j++) { float2 t = red[tid * 4 + j]; s += t.x; q += t.y; }
        float mean = s * (1.0f / E_);
        float var  = q * (1.0f / E_) - mean * mean;
        mr[tid] = make_float2(mean, rsqrtf(var + 1e-5f));
    }
    __syncthreads();

    float cf0 = 0.f, cf1 = 0.f;
    if constexpr (PROD == 0) {
        int c = (lane & 3) * 2;
        cf0 = __cosf(fTh[c]); cf1 = __cosf(fTh[c + 1]);
    }
    float ps[8][2];
    if constexpr (PROD == 2) {
#pragma unroll
        for (int ni = 0; ni < 8; ni++) { ps[ni][0] = 0.f; ps[ni][1] = 0.f; }
    }

#pragma unroll
    for (int mi = 0; mi < 4; mi++) {
        int rl = r0l + mi * 16;
        float2 m0 = mr[rl], m1 = mr[rl + 8];
        size_t ra = bm + rl;
#pragma unroll
        for (int ni = 0; ni < 8; ni++) {
            int col = mcol + ni * 8;
            float gx = lnG[col], gy = lnG[col + 1];
            float bx = lnB[col], by = lnB[col + 1];
            float o0 = (acc[mi][ni][0] - m0.x) * m0.y * gx + bx;
            float o1 = (acc[mi][ni][1] - m0.x) * m0.y * gy + by;
            float o2 = (acc[mi][ni][2] - m1.x) * m1.y * gx + bx;
            float o3 = (acc[mi][ni][3] - m1.x) * m1.y * gy + by;
            if constexpr (PROD != 2) {
                *(float2*)(g_x + ra * E_ + col) = make_float2(o0, o1);
                *(float2*)(g_x + (ra + 8) * E_ + col) = make_float2(o2, o3);
            }
            if constexpr (PROD == 0) {
                if (wn == 0 && ni == 0) {
                    int c = (lane & 3) * 2;
                    qsh[rl * 8 + c]           = __cosf(o0) * cf0;
                    qsh[rl * 8 + c + 1]       = __cosf(o1) * cf1;
                    qsh[(rl + 8) * 8 + c]     = __cosf(o2) * cf0;
                    qsh[(rl + 8) * 8 + c + 1] = __cosf(o3) * cf1;
                }
            }
            if constexpr (PROD == 1) {
                float t0 = thN[col & 63], t1 = thN[(col + 1) & 63];
                *(__half2*)(g_ah + ra * E_ + col) =
                    __halves2half2(__float2half_rn(__cosf(o0 + t0)),
                                   __float2half_rn(__cosf(o1 + t1)));
                *(__half2*)(g_ah + (ra + 8) * E_ + col) =
                    __halves2half2(__float2half_rn(__cosf(o2 + t0)),
                                   __float2half_rn(__cosf(o3 + t1)));
            }
            if constexpr (PROD == 2) {
                ps[ni][0] += o0 + o2;
                ps[ni][1] += o1 + o3;
            }
        }
    }

    if constexpr (PROD == 2) {
        // sum over r0l (lanes differing in bits 2..4) -> full 64-row col sums
#pragma unroll
        for (int ni = 0; ni < 8; ni++)
#pragma unroll
            for (int o = 4; o <= 16; o <<= 1) {
                ps[ni][0] += __shfl_xor_sync(0xffffffffu, ps[ni][0], o);
                ps[ni][1] += __shfl_xor_sync(0xffffffffu, ps[ni][1], o);
            }
        if (lane < 4) {
#pragma unroll
            for (int ni = 0; ni < 8; ni++) {
                g_pp[blockIdx.x * 256 + mcol + ni * 8]     = ps[ni][0];
                g_pp[blockIdx.x * 256 + mcol + ni * 8 + 1] = ps[ni][1];
            }
        }
    }
}

// ---------------- fused transformer layer: attn GEMM -> LN1 -> ffn -> LN2 ----
template <int LAYER>
__global__ void __launch_bounds__(128, 2)
k_layer(const __half* __restrict__ Ag,
        const __half* __restrict__ Wa, const __half* __restrict__ Wf,
        const float* __restrict__ cb,
        const float* __restrict__ ln1g, const float* __restrict__ ln1b,
        const float* __restrict__ fTh,
        const float* __restrict__ W1, const float* __restrict__ b1,
        const float* __restrict__ l2b,
        const float* __restrict__ ln2g, const float* __restrict__ ln2b,
        const float* __restrict__ thN) {
    extern __shared__ __align__(16) char smem[];
    uint32_t sb = s2u(smem);
    int tid = threadIdx.x;
    size_t bm = (size_t)blockIdx.x * 64;

    float* w1s = (float*)(smem + W1S_O);
    float* b1s = (float*)(smem + B1S_O);
    float* qsh = (float*)(smem + QSH_O);

    // stage W1 ([n][f] layout, same as global) + b1 — consumed in phase B
#pragma unroll
    for (int i = 0; i < 32; i++) w1s[tid + i * 128] = W1[tid + i * 128];
#pragma unroll
    for (int i = 0; i < 4; i++) b1s[tid + i * 128] = b1[tid + i * 128];

    float acc[4][8][4];
#pragma unroll
    for (int i = 0; i < 4; i++)
#pragma unroll
        for (int j = 0; j < 8; j++)
#pragma unroll
            for (int c = 0; c < 4; c++) acc[i][j][c] = 0.f;

    // phase A: attn GEMM (K=256, A from global)
    run_gemm<256, false>(acc, smem, sb, bm, Ag, Wa, nullptr, nullptr, nullptr);
    epilogue<0>(acc, smem, bm, cb, ln1g, ln1b, fTh, nullptr);
    __syncthreads();   // qsh ready for comp_h

    // phase B: ffn GEMM (K=512, A computed in-CTA)
#pragma unroll
    for (int i = 0; i < 4; i++)
#pragma unroll
        for (int j = 0; j < 8; j++)
#pragma unroll
            for (int c = 0; c < 4; c++) acc[i][j][c] = 0.f;
    run_gemm<512, true>(acc, smem, sb, bm, nullptr, Wf, qsh, w1s, b1s);
    if constexpr (LAYER == 0)
        epilogue<1>(acc, smem, bm, l2b, ln2g, ln2b, nullptr, thN);
    else
        epilogue<2>(acc, smem, bm, l2b, ln2g, ln2b, nullptr, nullptr);
}

// ---------------- classifier -------------------------------------------------
__global__ void k_cls(const float* __restrict__ w, const float* __restrict__ cb,
                      float* __restrict__ out) {
    __shared__ float sh[16];
    int b = blockIdx.x, e = threadIdx.x;
    float p = 0.f;
#pragma unroll 8
    for (int j = 0; j < 32; j++) p += g_pp[(b * 32 + j) * E_ + e];
    p *= (1.0f / (float)S_);
    float s0 = p * w[e * 2], s1 = p * w[e * 2 + 1];
    for (int o = 16; o > 0; o >>= 1) {
        s0 += __shfl_xor_sync(0xffffffffu, s0, o);
        s1 += __shfl_xor_sync(0xffffffffu, s1, o);
    }
    int wi = e >> 5;
    if ((e & 31) == 0) { sh[wi * 2] = s0; sh[wi * 2 + 1] = s1; }
    __syncthreads();
    if (e == 0) {
        float t0 = 0, t1 = 0;
#pragma unroll
        for (int j = 0; j < 8; j++) { t0 += sh[j * 2]; t1 += sh[j * 2 + 1]; }
        out[b * 2]     = t0 + cb[0];
        out[b * 2 + 1] = t1 + cb[1];
    }
}

// ---------------- host launcher ----------------------------------------------
extern "C" void kernel_launch(void* const* d_in, const int* in_sizes, int n_in,
                              void* d_out, int out_size) {
    const int*   tokens     = (const int*)d_in[0];
    const float* embed      = (const float*)d_in[1];
    const float* attn_theta = (const float*)d_in[2];
    const float* combine_w  = (const float*)d_in[3];
    const float* combine_b  = (const float*)d_in[4];
    const float* ffn_theta  = (const float*)d_in[5];
    const float* lin1_w     = (const float*)d_in[6];
    const float* lin1_b     = (const float*)d_in[7];
    const float* lin2_w     = (const float*)d_in[8];
    const float* lin2_b     = (const float*)d_in[9];
    const float* ln1_g      = (const float*)d_in[10];
    const float* ln1_b      = (const float*)d_in[11];
    const float* ln2_g      = (const float*)d_in[12];
    const float* ln2_b      = (const float*)d_in[13];
    const float* cls_w      = (const float*)d_in[14];
    const float* cls_b      = (const float*)d_in[15];
    float* out = (float*)d_out;

    __half *ah, *wh;
    cudaGetSymbolAddress((void**)&ah, g_ah);
    cudaGetSymbolAddress((void**)&wh, g_wh);

    cudaFuncSetAttribute(k_layer<0>, cudaFuncAttributeMaxDynamicSharedMemorySize, SME_T);
    cudaFuncSetAttribute(k_layer<1>, cudaFuncAttributeMaxDynamicSharedMemorySize, SME_T);

    k_embed<<<M_, 256>>>(tokens, embed, attn_theta);
    k_convw<<<dim3(256, 4), 256>>>(combine_w, lin2_w);

    k_layer<0><<<M_ / 64, 128, SME_T>>>(
        ah, wh + 0 * 131072, wh + 2 * 131072,
        combine_b, ln1_g, ln1_b,
        ffn_theta, lin1_w, lin1_b,
        lin2_b, ln2_g, ln2_b, attn_theta + 64);
    k_layer<1><<<M_ / 64, 128, SME_T>>>(
        ah, wh + 1 * 131072, wh + 3 * 131072,
        combine_b + E_, ln1_g + E_, ln1_b + E_,
        ffn_theta + NQ_, lin1_w + NQ_ * FFN_, lin1_b + FFN_,
        lin2_b + E_, ln2_g + E_, ln2_b + E_, nullptr);

    k_cls<<<B_, 256>>>(cls_w, cls_b, out);
}

// round 15
// speedup vs baseline: 1.8219x; 1.0730x over previous
#include <cuda_runtime.h>
#include <cuda_fp16.h>
#include <cstdint>
#include <math.h>

#define B_   16
#define S_   2048
#define E_   256
#define L_   2
#define NQ_  8
#define FFN_ 512
#define C_   2
#define M_   (B_*S_)   // 32768 rows

// ---------------- scratch (__device__ globals; no allocations) ---------------
__device__ float g_x[(size_t)M_*E_];                      // 32 MB
__device__ __align__(128) __half g_ah[(size_t)M_*E_];     // 16 MB  attn A (fp16)
__device__ __align__(128) __half g_wh[4*256*512];         // Wt[n][k] fp16
__device__ float g_pp[512*E_];                            // pool partials

// ---------------- smem layout (bytes) ----------------------------------------
// stages: [0, 61440)  (3 x 20480, all phases)
#define W1S0_O  61440   // [8][512] float, layer0, 16384 B
#define B1S0_O  77824   // [512] float, 2048 B
#define W1S1_O  79872   // [8][512] float, layer1, 16384 B
#define B1S1_O  96256   // [512] float, 2048 B
#define QSH_O   98304   // [64][8] float, 2048 B
#define RED_O   100352  // [64][4] float2, 2048 B
#define MR_O    102400  // [64] float2, 512 B
#define SME_T   102912

// ---------------- PTX helpers ------------------------------------------------
__device__ __forceinline__ uint32_t s2u(const void* p) {
    uint32_t a;
    asm("{ .reg .u64 t; cvta.to.shared.u64 t, %1; cvt.u32.u64 %0, t; }"
        : "=r"(a) : "l"(p));
    return a;
}
__device__ __forceinline__ void cp16(uint32_t dst, const void* src) {
    asm volatile("cp.async.cg.shared.global [%0], [%1], 16;" :: "r"(dst), "l"(src));
}
__device__ __forceinline__ void cp_commit() {
    asm volatile("cp.async.commit_group;" ::: "memory");
}
__device__ __forceinline__ void cp_wait1() {
    asm volatile("cp.async.wait_group 1;" ::: "memory");
}
__device__ __forceinline__ void cp_wait0() {
    asm volatile("cp.async.wait_group 0;" ::: "memory");
}
__device__ __forceinline__ void ldm_x4(uint32_t& r0, uint32_t& r1, uint32_t& r2,
                                       uint32_t& r3, uint32_t addr) {
    asm volatile("ldmatrix.sync.aligned.m8n8.x4.shared.b16 {%0,%1,%2,%3}, [%4];"
                 : "=r"(r0), "=r"(r1), "=r"(r2), "=r"(r3) : "r"(addr));
}
__device__ __forceinline__ void mma16816(float* c, uint32_t a0, uint32_t a1,
                                         uint32_t a2, uint32_t a3,
                                         uint32_t b0, uint32_t b1) {
    asm volatile(
        "mma.sync.aligned.m16n8k16.row.col.f32.f16.f16.f32 "
        "{%0,%1,%2,%3}, {%4,%5,%6,%7}, {%8,%9}, {%0,%1,%2,%3};"
        : "+f"(c[0]), "+f"(c[1]), "+f"(c[2]), "+f"(c[3])
        : "r"(a0), "r"(a1), "r"(a2), "r"(a3), "r"(b0), "r"(b1));
}

// ---------------- weight convert + transpose (fp16) --------------------------
__global__ void k_convw(const float* __restrict__ cw, const float* __restrict__ l2w) {
    int slot = blockIdx.y;
    int n    = blockIdx.x;
    int K    = (slot < 2) ? 256 : 512;
    const float* src = (slot < 2) ? (cw + (size_t)slot * E_ * E_)
                                  : (l2w + (size_t)(slot - 2) * FFN_ * E_);
    for (int k = threadIdx.x; k < K; k += 256) {
        float w = src[(size_t)k * E_ + n];
        g_wh[(size_t)slot * 131072 + (size_t)n * K + k] = __float2half_rn(w);
    }
}

// ---------------- GEMM phase: BM=64, BN=256, BK=32, 128 thr ------------------
// 4 warps, warp tile 64x64. Per k16: 8 ldmatrix.x4 -> 32 MMAs. 64B rows,
// XOR-4 swizzle, 3-stage pipeline, 1 barrier/chunk.
// COMPA: A chunk computed in-CTA from q @ W1 + b1 (relu, fp16).
template <int K, bool COMPA>
__device__ __forceinline__ void run_gemm(
    float (&acc)[4][8][4], char* smem, uint32_t sb, size_t bm,
    const __half* __restrict__ Ag, const __half* __restrict__ W,
    const float* qsh, const float* w1s, const float* b1s) {
    constexpr int CH    = K >> 5;
    constexpr int W_O   = 4096;
    constexpr int STAGE = 20480;
    int tid = threadIdx.x, lane = tid & 31, wn = tid >> 5;

    int part = tid & 3, rb = tid >> 2;                    // rb 0..31

    auto load_stage = [&](int st, int ch) {
        uint32_t dst = sb + st * STAGE;
        int kk = ch << 5;
        if constexpr (!COMPA) {
#pragma unroll
            for (int i = 0; i < 2; i++) {
                int r = rb + i * 32;
                uint32_t sw = (uint32_t)(part ^ ((r >> 1) & 3)) << 4;
                cp16(dst + r * 64 + sw, Ag + (bm + r) * (size_t)K + kk + part * 8);
            }
        }
#pragma unroll
        for (int i = 0; i < 8; i++) {
            int r = rb + i * 32;
            uint32_t sw = (uint32_t)(part ^ ((r >> 1) & 3)) << 4;
            cp16(dst + W_O + r * 64 + sw, W + (size_t)r * K + kk + part * 8);
        }
        cp_commit();
    };

    auto comp_h = [&](int st, int ch) {
        if constexpr (COMPA) {
            char* dst = smem + st * STAGE;
            int r = tid >> 1, half = tid & 1;             // r 0..63
            int f0 = (ch << 5) + half * 16;
            float qr[8];
#pragma unroll
            for (int n = 0; n < 8; n++) qr[n] = qsh[r * 8 + n];
            __half2 hp[8];
#pragma unroll
            for (int jj = 0; jj < 8; jj++) {
                float hv[2];
#pragma unroll
                for (int u = 0; u < 2; u++) {
                    int f = f0 + jj * 2 + u;
                    float h = b1s[f];
#pragma unroll
                    for (int n = 0; n < 8; n++) h += qr[n] * w1s[n * 512 + f];
                    hv[u] = fmaxf(h, 0.f);
                }
                hp[jj] = __halves2half2(__float2half_rn(hv[0]),
                                        __float2half_rn(hv[1]));
            }
            uint32_t swz = (uint32_t)((r >> 1) & 3);
            uint32_t o0 = (uint32_t)r * 64 + (((uint32_t)(half * 2)     ^ swz) << 4);
            uint32_t o1 = (uint32_t)r * 64 + (((uint32_t)(half * 2 + 1) ^ swz) << 4);
            *(uint4*)(dst + o0) = *(uint4*)&hp[0];
            *(uint4*)(dst + o1) = *(uint4*)&hp[4];
        }
    };

    load_stage(0, 0); comp_h(0, 0);
    load_stage(1, 1); comp_h(1, 1);

    uint32_t rowA = lane & 15;
    uint32_t rxA  = (rowA >> 1) & 3;
    uint32_t cA   = (uint32_t)lane >> 4;
    uint32_t rowB = wn * 64 + ((lane >> 4) & 1) * 8 + (lane & 7);
    uint32_t rxB  = (rowB >> 1) & 3;
    uint32_t cB   = ((uint32_t)lane >> 3) & 1;

    int st = 0;
    for (int cc = 0; cc < CH; cc++) {
        if (cc + 1 < CH) cp_wait1(); else cp_wait0();
        __syncthreads();
        if (cc + 2 < CH) {
            int st2 = st + 2; if (st2 >= 3) st2 -= 3;
            load_stage(st2, cc + 2);
            comp_h(st2, cc + 2);
        }
        uint32_t stg = sb + st * STAGE;
        uint32_t aB  = stg + rowA * 64;
        uint32_t bB  = stg + W_O + rowB * 64;

#pragma unroll
        for (int kb = 0; kb < 2; kb++) {
            uint32_t colA = (((uint32_t)(kb * 2) + cA) ^ rxA) << 4;
            uint32_t colB = (((uint32_t)(kb * 2) + cB) ^ rxB) << 4;
            uint32_t b[16];
#pragma unroll
            for (int n2 = 0; n2 < 4; n2++)
                ldm_x4(b[n2*4], b[n2*4+1], b[n2*4+2], b[n2*4+3],
                       bB + n2 * 1024 + colB);
            uint32_t a0[4], a1[4], a2[4], a3[4];
#pragma unroll
            for (int mi = 0; mi < 4; mi++)
                ldm_x4(a0[mi], a1[mi], a2[mi], a3[mi], aB + mi * 1024 + colA);
#pragma unroll
            for (int mi = 0; mi < 4; mi++)
#pragma unroll
                for (int n2 = 0; n2 < 4; n2++) {
                    mma16816(acc[mi][n2*2],   a0[mi], a1[mi], a2[mi], a3[mi],
                             b[n2*4],   b[n2*4+1]);
                    mma16816(acc[mi][n2*2+1], a0[mi], a1[mi], a2[mi], a3[mi],
                             b[n2*4+2], b[n2*4+3]);
                }
        }
        if (++st == 3) st = 0;
    }
    __syncthreads();   // all stage-buffer reads done before buffers reused
}

// ---------------- epilogue: residual + LN (+ producer) -----------------------
// PROD 0: write g_x + q->qsh.  PROD 1: write g_x + next-layer A (fp16).
// PROD 2: pool partials only.
template <int PROD>
__device__ __forceinline__ void epilogue(
    float (&acc)[4][8][4], char* smem, size_t bm,
    const float* __restrict__ bias,
    const float* __restrict__ lnG, const float* __restrict__ lnB,
    const float* __restrict__ fTh, const float* __restrict__ thN) {
    float2* red = (float2*)(smem + RED_O);
    float2* mr  = (float2*)(smem + MR_O);
    float*  qsh = (float*)(smem + QSH_O);
    int tid = threadIdx.x, lane = tid & 31, wn = tid >> 5;
    int mcol = wn * 64 + (lane & 3) * 2;
    int r0l  = lane >> 2;                                 // 0..7

#pragma unroll
    for (int mi = 0; mi < 4; mi++) {
        float s0 = 0, q0 = 0, s1 = 0, q1 = 0;
        size_t ra = bm + r0l + mi * 16;
#pragma unroll
        for (int ni = 0; ni < 8; ni++) {
            int col = mcol + ni * 8;
            float2 x0 = *(const float2*)(g_x + ra * E_ + col);
            float2 x1 = *(const float2*)(g_x + (ra + 8) * E_ + col);
            float bcx = bias[col], bcy = bias[col + 1];
            float v0 = acc[mi][ni][0] + bcx + x0.x;
            float v1 = acc[mi][ni][1] + bcy + x0.y;
            float v2 = acc[mi][ni][2] + bcx + x1.x;
            float v3 = acc[mi][ni][3] + bcy + x1.y;
            acc[mi][ni][0] = v0; acc[mi][ni][1] = v1;
            acc[mi][ni][2] = v2; acc[mi][ni][3] = v3;
            s0 += v0 + v1; q0 += v0 * v0 + v1 * v1;
            s1 += v2 + v3; q1 += v2 * v2 + v3 * v3;
        }
#pragma unroll
        for (int o = 1; o <= 2; o <<= 1) {
            s0 += __shfl_xor_sync(0xffffffffu, s0, o);
            q0 += __shfl_xor_sync(0xffffffffu, q0, o);
            s1 += __shfl_xor_sync(0xffffffffu, s1, o);
            q1 += __shfl_xor_sync(0xffffffffu, q1, o);
        }
        if ((lane & 3) == 0) {
            int rl = r0l + mi * 16;
            red[rl * 4 + wn] = make_float2(s0, q0);
            red[(rl + 8) * 4 + wn] = make_float2(s1, q1);
        }
    }
    __syncthreads();
    if (tid < 64) {
        float s = 0, q = 0;
#pragma unroll
        for (int j = 0; j < 4; j++) { float2 t = red[tid * 4 + j]; s += t.x; q += t.y; }
        float mean = s * (1.0f / E_);
        float var  = q * (1.0f / E_) - mean * mean;
        mr[tid] = make_float2(mean, rsqrtf(var + 1e-5f));
    }
    __syncthreads();

    float cf0 = 0.f, cf1 = 0.f;
    if constexpr (PROD == 0) {
        int c = (lane & 3) * 2;
        cf0 = __cosf(fTh[c]); cf1 = __cosf(fTh[c + 1]);
    }
    float ps[8][2];
    if constexpr (PROD == 2) {
#pragma unroll
        for (int ni = 0; ni < 8; ni++) { ps[ni][0] = 0.f; ps[ni][1] = 0.f; }
    }

#pragma unroll
    for (int mi = 0; mi < 4; mi++) {
        int rl = r0l + mi * 16;
        float2 m0 = mr[rl], m1 = mr[rl + 8];
        size_t ra = bm + rl;
#pragma unroll
        for (int ni = 0; ni < 8; ni++) {
            int col = mcol + ni * 8;
            float gx = lnG[col], gy = lnG[col + 1];
            float bx = lnB[col], by = lnB[col + 1];
            float o0 = (acc[mi][ni][0] - m0.x) * m0.y * gx + bx;
            float o1 = (acc[mi][ni][1] - m0.x) * m0.y * gy + by;
            float o2 = (acc[mi][ni][2] - m1.x) * m1.y * gx + bx;
            float o3 = (acc[mi][ni][3] - m1.x) * m1.y * gy + by;
            if constexpr (PROD != 2) {
                *(float2*)(g_x + ra * E_ + col) = make_float2(o0, o1);
                *(float2*)(g_x + (ra + 8) * E_ + col) = make_float2(o2, o3);
            }
            if constexpr (PROD == 0) {
                if (wn == 0 && ni == 0) {
                    int c = (lane & 3) * 2;
                    qsh[rl * 8 + c]           = __cosf(o0) * cf0;
                    qsh[rl * 8 + c + 1]       = __cosf(o1) * cf1;
                    qsh[(rl + 8) * 8 + c]     = __cosf(o2) * cf0;
                    qsh[(rl + 8) * 8 + c + 1] = __cosf(o3) * cf1;
                }
            }
            if constexpr (PROD == 1) {
                float t0 = thN[col & 63], t1 = thN[(col + 1) & 63];
                *(__half2*)(g_ah + ra * E_ + col) =
                    __halves2half2(__float2half_rn(__cosf(o0 + t0)),
                                   __float2half_rn(__cosf(o1 + t1)));
                *(__half2*)(g_ah + (ra + 8) * E_ + col) =
                    __halves2half2(__float2half_rn(__cosf(o2 + t0)),
                                   __float2half_rn(__cosf(o3 + t1)));
            }
            if constexpr (PROD == 2) {
                ps[ni][0] += o0 + o2;
                ps[ni][1] += o1 + o3;
            }
        }
    }

    if constexpr (PROD == 2) {
#pragma unroll
        for (int ni = 0; ni < 8; ni++)
#pragma unroll
            for (int o = 4; o <= 16; o <<= 1) {
                ps[ni][0] += __shfl_xor_sync(0xffffffffu, ps[ni][0], o);
                ps[ni][1] += __shfl_xor_sync(0xffffffffu, ps[ni][1], o);
            }
        if (lane < 4) {
#pragma unroll
            for (int ni = 0; ni < 8; ni++) {
                g_pp[blockIdx.x * 256 + mcol + ni * 8]     = ps[ni][0];
                g_pp[blockIdx.x * 256 + mcol + ni * 8 + 1] = ps[ni][1];
            }
        }
    }
}

// ---------------- whole network: embed + 2 fused layers ----------------------
__global__ void __launch_bounds__(128, 2)
k_net(const int* __restrict__ tokens, const float* __restrict__ emb,
      const float* __restrict__ attn_theta,
      const float* __restrict__ combine_b,
      const float* __restrict__ ffn_theta,
      const float* __restrict__ lin1_w, const float* __restrict__ lin1_b,
      const float* __restrict__ lin2_b,
      const float* __restrict__ ln1_g, const float* __restrict__ ln1_b,
      const float* __restrict__ ln2_g, const float* __restrict__ ln2_b) {
    extern __shared__ __align__(16) char smem[];
    uint32_t sb = s2u(smem);
    int tid = threadIdx.x;
    size_t bm = (size_t)blockIdx.x * 64;
    const __half* wh = g_wh;

    // stage W1/b1 for both layers
    float* w1s0 = (float*)(smem + W1S0_O);
    float* b1s0 = (float*)(smem + B1S0_O);
    float* w1s1 = (float*)(smem + W1S1_O);
    float* b1s1 = (float*)(smem + B1S1_O);
    float* qsh  = (float*)(smem + QSH_O);
#pragma unroll
    for (int i = 0; i < 32; i++) {
        w1s0[tid + i * 128] = lin1_w[tid + i * 128];
        w1s1[tid + i * 128] = lin1_w[NQ_ * FFN_ + tid + i * 128];
    }
#pragma unroll
    for (int i = 0; i < 4; i++) {
        b1s0[tid + i * 128] = lin1_b[tid + i * 128];
        b1s1[tid + i * 128] = lin1_b[FFN_ + tid + i * 128];
    }

    // ---- embed prologue: rows bm..bm+63 (CTA-local) ----
    {
        const float* th0 = attn_theta;
#pragma unroll
        for (int i = 0; i < 32; i++) {
            int idx = tid + i * 128;            // 0..4095 float4s
            int r   = idx >> 6;                 // 0..63
            int c   = (idx & 63) * 4;
            size_t row = bm + r;
            int s = (int)(row & (S_ - 1));
            int t = tokens[row];
            float4 ev = *(const float4*)(emb + (size_t)t * E_ + c);
            float xs[4]; float av[4];
#pragma unroll
            for (int j = 0; j < 4; j++) {
                int e = c + j;
                float freq = __expf(-(float)(e & ~1) * (9.210340371976184f / (float)E_));
                float ang  = (float)s * freq;
                float pe   = (e & 1) ? __cosf(ang) : __sinf(ang);
                float x = ((const float*)&ev)[j] + pe;
                xs[j] = x;
                av[j] = __cosf(x + th0[e & 63]);
            }
            *(float4*)(g_x + row * E_ + c) = make_float4(xs[0], xs[1], xs[2], xs[3]);
            __half2 h01 = __halves2half2(__float2half_rn(av[0]), __float2half_rn(av[1]));
            __half2 h23 = __halves2half2(__float2half_rn(av[2]), __float2half_rn(av[3]));
            *(uint2*)(g_ah + row * E_ + c) = make_uint2(
                *(uint32_t*)&h01, *(uint32_t*)&h23);
        }
    }
    __syncthreads();

    float acc[4][8][4];
#pragma unroll
    for (int l = 0; l < L_; l++) {
        const __half* Wa = wh + (size_t)l * 131072;
        const __half* Wf = wh + (size_t)(2 + l) * 131072;
        const float* w1s = l ? w1s1 : w1s0;
        const float* b1s = l ? b1s1 : b1s0;

        // attn GEMM (K=256, A from g_ah)
#pragma unroll
        for (int i = 0; i < 4; i++)
#pragma unroll
            for (int j = 0; j < 8; j++)
#pragma unroll
                for (int c = 0; c < 4; c++) acc[i][j][c] = 0.f;
        run_gemm<256, false>(acc, smem, sb, bm, g_ah, Wa, nullptr, nullptr, nullptr);
        epilogue<0>(acc, smem, bm, combine_b + l * E_,
                    ln1_g + l * E_, ln1_b + l * E_, ffn_theta + l * NQ_, nullptr);
        __syncthreads();   // qsh ready

        // ffn GEMM (K=512, A computed in-CTA)
#pragma unroll
        for (int i = 0; i < 4; i++)
#pragma unroll
            for (int j = 0; j < 8; j++)
#pragma unroll
                for (int c = 0; c < 4; c++) acc[i][j][c] = 0.f;
        run_gemm<512, true>(acc, smem, sb, bm, nullptr, Wf, qsh, w1s, b1s);
        if (l == 0) {
            epilogue<1>(acc, smem, bm, lin2_b,
                        ln2_g, ln2_b, nullptr, attn_theta + 64);
            __syncthreads();   // g_ah rows written before next attn reads them
        } else {
            epilogue<2>(acc, smem, bm, lin2_b + E_,
                        ln2_g + E_, ln2_b + E_, nullptr, nullptr);
        }
    }
}

// ---------------- classifier -------------------------------------------------
__global__ void k_cls(const float* __restrict__ w, const float* __restrict__ cb,
                      float* __restrict__ out) {
    __shared__ float sh[16];
    int b = blockIdx.x, e = threadIdx.x;
    float p = 0.f;
#pragma unroll 8
    for (int j = 0; j < 32; j++) p += g_pp[(b * 32 + j) * E_ + e];
    p *= (1.0f / (float)S_);
    float s0 = p * w[e * 2], s1 = p * w[e * 2 + 1];
    for (int o = 16; o > 0; o >>= 1) {
        s0 += __shfl_xor_sync(0xffffffffu, s0, o);
        s1 += __shfl_xor_sync(0xffffffffu, s1, o);
    }
    int wi = e >> 5;
    if ((e & 31) == 0) { sh[wi * 2] = s0; sh[wi * 2 + 1] = s1; }
    __syncthreads();
    if (e == 0) {
        float t0 = 0, t1 = 0;
#pragma unroll
        for (int j = 0; j < 8; j++) { t0 += sh[j * 2]; t1 += sh[j * 2 + 1]; }
        out[b * 2]     = t0 + cb[0];
        out[b * 2 + 1] = t1 + cb[1];
    }
}

// ---------------- host launcher ----------------------------------------------
extern "C" void kernel_launch(void* const* d_in, const int* in_sizes, int n_in,
                              void* d_out, int out_size) {
    const int*   tokens     = (const int*)d_in[0];
    const float* embed      = (const float*)d_in[1];
    const float* attn_theta = (const float*)d_in[2];
    const float* combine_w  = (const float*)d_in[3];
    const float* combine_b  = (const float*)d_in[4];
    const float* ffn_theta  = (const float*)d_in[5];
    const float* lin1_w     = (const float*)d_in[6];
    const float* lin1_b     = (const float*)d_in[7];
    const float* lin2_w     = (const float*)d_in[8];
    const float* lin2_b     = (const float*)d_in[9];
    const float* ln1_g      = (const float*)d_in[10];
    const float* ln1_b      = (const float*)d_in[11];
    const float* ln2_g      = (const float*)d_in[12];
    const float* ln2_b      = (const float*)d_in[13];
    const float* cls_w      = (const float*)d_in[14];
    const float* cls_b      = (const float*)d_in[15];
    float* out = (float*)d_out;

    cudaFuncSetAttribute(k_net, cudaFuncAttributeMaxDynamicSharedMemorySize, SME_T);

    k_convw<<<dim3(256, 4), 256>>>(combine_w, lin2_w);
    k_net<<<M_ / 64, 128, SME_T>>>(tokens, embed, attn_theta, combine_b,
                                   ffn_theta, lin1_w, lin1_b, lin2_b,
                                   ln1_g, ln1_b, ln2_g, ln2_b);
    k_cls<<<B_, 256>>>(cls_w, cls_b, out);
}

// round 16
// speedup vs baseline: 1.9989x; 1.0971x over previous
#include <cuda_runtime.h>
#include <cuda_fp16.h>
#include <cstdint>
#include <math.h>

#define B_   16
#define S_   2048
#define E_   256
#define L_   2
#define NQ_  8
#define FFN_ 512
#define C_   2
#define M_   (B_*S_)   // 32768 rows

// ---------------- scratch (__device__ globals; no allocations) ---------------
__device__ __align__(128) __half g_wh[4*256*512];         // Wt[n][k] fp16
__device__ float g_pp[512*E_];                            // pool partials

// ---------------- smem layout (bytes) ----------------------------------------
#define STAGE   20480   // A 4096 + W 16384 per stage; 2 stages
#define XRES_O  40960   // [64][256] fp16 residual x, 32768 B
#define W1S_O   73728   // [8][512] float ([n][f]), current layer, 16384 B
#define B1S_O   90112   // [512] float, 2048 B
#define QSH_O   92160   // [64][8] float, 2048 B
#define RED_O   94208   // [64][4] float2, 2048 B
#define MR_O    96256   // [64] float2, 512 B
#define SME_T   96768

// ---------------- PTX helpers ------------------------------------------------
__device__ __forceinline__ uint32_t s2u(const void* p) {
    uint32_t a;
    asm("{ .reg .u64 t; cvta.to.shared.u64 t, %1; cvt.u32.u64 %0, t; }"
        : "=r"(a) : "l"(p));
    return a;
}
__device__ __forceinline__ void cp16(uint32_t dst, const void* src) {
    asm volatile("cp.async.cg.shared.global [%0], [%1], 16;" :: "r"(dst), "l"(src));
}
__device__ __forceinline__ void cp_commit() {
    asm volatile("cp.async.commit_group;" ::: "memory");
}
__device__ __forceinline__ void cp_wait0() {
    asm volatile("cp.async.wait_group 0;" ::: "memory");
}
__device__ __forceinline__ void ldm_x4(uint32_t& r0, uint32_t& r1, uint32_t& r2,
                                       uint32_t& r3, uint32_t addr) {
    asm volatile("ldmatrix.sync.aligned.m8n8.x4.shared.b16 {%0,%1,%2,%3}, [%4];"
                 : "=r"(r0), "=r"(r1), "=r"(r2), "=r"(r3) : "r"(addr));
}
__device__ __forceinline__ void mma16816(float* c, uint32_t a0, uint32_t a1,
                                         uint32_t a2, uint32_t a3,
                                         uint32_t b0, uint32_t b1) {
    asm volatile(
        "mma.sync.aligned.m16n8k16.row.col.f32.f16.f16.f32 "
        "{%0,%1,%2,%3}, {%4,%5,%6,%7}, {%8,%9}, {%0,%1,%2,%3};"
        : "+f"(c[0]), "+f"(c[1]), "+f"(c[2]), "+f"(c[3])
        : "r"(a0), "r"(a1), "r"(a2), "r"(a3), "r"(b0), "r"(b1));
}

// ---------------- weight convert + transpose (fp16) --------------------------
__global__ void k_convw(const float* __restrict__ cw, const float* __restrict__ l2w) {
    int slot = blockIdx.y;
    int n    = blockIdx.x;
    int K    = (slot < 2) ? 256 : 512;
    const float* src = (slot < 2) ? (cw + (size_t)slot * E_ * E_)
                                  : (l2w + (size_t)(slot - 2) * FFN_ * E_);
    for (int k = threadIdx.x; k < K; k += 256) {
        float w = src[(size_t)k * E_ + n];
        g_wh[(size_t)slot * 131072 + (size_t)n * K + k] = __float2half_rn(w);
    }
}

// ---------------- GEMM phase: BM=64, BN=256, BK=32, 128 thr ------------------
// 4 warps, warp tile 64x64. A chunk computed in-CTA each chunk:
//   SRC 0: a = cos(xres + theta[k&63])   (attn)
//   SRC 1: a = relu(q @ W1 + b1) fp16    (ffn)
// W loaded via cp.async (only global traffic). 64B rows, XOR-4 swizzle,
// 2-stage pipeline, 1 barrier/chunk.
template <int K, int SRC>
__device__ __forceinline__ void run_gemm(
    float (&acc)[4][8][4], char* smem, uint32_t sb,
    const float* __restrict__ th, const __half* __restrict__ W,
    const float* qsh, const float* w1s, const float* b1s) {
    constexpr int CH  = K >> 5;
    constexpr int W_O = 4096;
    int tid = threadIdx.x, lane = tid & 31, wn = tid >> 5;
    int part = tid & 3, rb = tid >> 2;                    // rb 0..31

    auto load_stage = [&](int st, int ch) {
        uint32_t dst = sb + st * STAGE;
        int kk = ch << 5;
#pragma unroll
        for (int i = 0; i < 8; i++) {
            int r = rb + i * 32;
            uint32_t sw = (uint32_t)(part ^ ((r >> 1) & 3)) << 4;
            cp16(dst + W_O + r * 64 + sw, W + (size_t)r * K + kk + part * 8);
        }
        cp_commit();
    };

    auto comp_src = [&](int st, int ch) {
        char* dst = smem + st * STAGE;
        int r = tid >> 1, half = tid & 1;                 // r 0..63
        int k0 = (ch << 5) + half * 16;
        __half2 hp[8];
        if constexpr (SRC == 0) {
            const __half2* xr = (const __half2*)(smem + XRES_O + r * 512
                                                 + (size_t)((k0 & 511) * 2));
#pragma unroll
            for (int j = 0; j < 8; j++) {
                float2 xv = __half22float2(xr[j]);
                int k = k0 + j * 2;
                hp[j] = __halves2half2(
                    __float2half_rn(__cosf(xv.x + th[k & 63])),
                    __float2half_rn(__cosf(xv.y + th[(k + 1) & 63])));
            }
        } else {
            float qr[8];
#pragma unroll
            for (int n = 0; n < 8; n++) qr[n] = qsh[r * 8 + n];
#pragma unroll
            for (int j = 0; j < 8; j++) {
                float hv[2];
#pragma unroll
                for (int u = 0; u < 2; u++) {
                    int f = k0 + j * 2 + u;
                    float h = b1s[f];
#pragma unroll
                    for (int n = 0; n < 8; n++) h += qr[n] * w1s[n * 512 + f];
                    hv[u] = fmaxf(h, 0.f);
                }
                hp[j] = __halves2half2(__float2half_rn(hv[0]),
                                       __float2half_rn(hv[1]));
            }
        }
        uint32_t swz = (uint32_t)((r >> 1) & 3);
        uint32_t o0 = (uint32_t)r * 64 + (((uint32_t)(half * 2)     ^ swz) << 4);
        uint32_t o1 = (uint32_t)r * 64 + (((uint32_t)(half * 2 + 1) ^ swz) << 4);
        *(uint4*)(dst + o0) = *(uint4*)&hp[0];
        *(uint4*)(dst + o1) = *(uint4*)&hp[4];
    };

    load_stage(0, 0);
    comp_src(0, 0);

    uint32_t rowA = lane & 15;
    uint32_t rxA  = (rowA >> 1) & 3;
    uint32_t cA   = (uint32_t)lane >> 4;
    uint32_t rowB = wn * 64 + ((lane >> 4) & 1) * 8 + (lane & 7);
    uint32_t rxB  = (rowB >> 1) & 3;
    uint32_t cB   = ((uint32_t)lane >> 3) & 1;

    for (int cc = 0; cc < CH; cc++) {
        cp_wait0();
        __syncthreads();
        if (cc + 1 < CH) {
            load_stage((cc + 1) & 1, cc + 1);
            comp_src((cc + 1) & 1, cc + 1);
        }
        uint32_t stg = sb + (cc & 1) * STAGE;
        uint32_t aB  = stg + rowA * 64;
        uint32_t bB  = stg + W_O + rowB * 64;

#pragma unroll
        for (int kb = 0; kb < 2; kb++) {
            uint32_t colA = (((uint32_t)(kb * 2) + cA) ^ rxA) << 4;
            uint32_t colB = (((uint32_t)(kb * 2) + cB) ^ rxB) << 4;
            uint32_t b[16];
#pragma unroll
            for (int n2 = 0; n2 < 4; n2++)
                ldm_x4(b[n2*4], b[n2*4+1], b[n2*4+2], b[n2*4+3],
                       bB + n2 * 1024 + colB);
            uint32_t a0[4], a1[4], a2[4], a3[4];
#pragma unroll
            for (int mi = 0; mi < 4; mi++)
                ldm_x4(a0[mi], a1[mi], a2[mi], a3[mi], aB + mi * 1024 + colA);
#pragma unroll
            for (int mi = 0; mi < 4; mi++)
#pragma unroll
                for (int n2 = 0; n2 < 4; n2++) {
                    mma16816(acc[mi][n2*2],   a0[mi], a1[mi], a2[mi], a3[mi],
                             b[n2*4],   b[n2*4+1]);
                    mma16816(acc[mi][n2*2+1], a0[mi], a1[mi], a2[mi], a3[mi],
                             b[n2*4+2], b[n2*4+3]);
                }
        }
    }
    __syncthreads();   // stage-buffer reads done before reuse
}

// ---------------- epilogue: residual(smem) + LN (+ producer) -----------------
// PROD 0: write xres + q->qsh.  PROD 1: write xres.  PROD 2: pool partials.
template <int PROD>
__device__ __forceinline__ void epilogue(
    float (&acc)[4][8][4], char* smem,
    const float* __restrict__ bias,
    const float* __restrict__ lnG, const float* __restrict__ lnB,
    const float* __restrict__ fTh) {
    float2*  red = (float2*)(smem + RED_O);
    float2*  mr  = (float2*)(smem + MR_O);
    float*   qsh = (float*)(smem + QSH_O);
    __half2* xr  = (__half2*)(smem + XRES_O);
    int tid = threadIdx.x, lane = tid & 31, wn = tid >> 5;
    int mcol = wn * 64 + (lane & 3) * 2;
    int r0l  = lane >> 2;                                 // 0..7

#pragma unroll
    for (int mi = 0; mi < 4; mi++) {
        float s0 = 0, q0 = 0, s1 = 0, q1 = 0;
        int rl = r0l + mi * 16;
#pragma unroll
        for (int ni = 0; ni < 8; ni++) {
            int col = mcol + ni * 8;
            float2 x0 = __half22float2(xr[rl * 128 + (col >> 1)]);
            float2 x1 = __half22float2(xr[(rl + 8) * 128 + (col >> 1)]);
            float bcx = bias[col], bcy = bias[col + 1];
            float v0 = acc[mi][ni][0] + bcx + x0.x;
            float v1 = acc[mi][ni][1] + bcy + x0.y;
            float v2 = acc[mi][ni][2] + bcx + x1.x;
            float v3 = acc[mi][ni][3] + bcy + x1.y;
            acc[mi][ni][0] = v0; acc[mi][ni][1] = v1;
            acc[mi][ni][2] = v2; acc[mi][ni][3] = v3;
            s0 += v0 + v1; q0 += v0 * v0 + v1 * v1;
            s1 += v2 + v3; q1 += v2 * v2 + v3 * v3;
        }
#pragma unroll
        for (int o = 1; o <= 2; o <<= 1) {
            s0 += __shfl_xor_sync(0xffffffffu, s0, o);
            q0 += __shfl_xor_sync(0xffffffffu, q0, o);
            s1 += __shfl_xor_sync(0xffffffffu, s1, o);
            q1 += __shfl_xor_sync(0xffffffffu, q1, o);
        }
        if ((lane & 3) == 0) {
            red[rl * 4 + wn] = make_float2(s0, q0);
            red[(rl + 8) * 4 + wn] = make_float2(s1, q1);
        }
    }
    __syncthreads();
    if (tid < 64) {
        float s = 0, q = 0;
#pragma unroll
        for (int j = 0; j < 4; j++) { float2 t = red[tid * 4 + j]; s += t.x; q += t.y; }
        float mean = s * (1.0f / E_);
        float var  = q * (1.0f / E_) - mean * mean;
        mr[tid] = make_float2(mean, rsqrtf(var + 1e-5f));
    }
    __syncthreads();

    float cf0 = 0.f, cf1 = 0.f;
    if constexpr (PROD == 0) {
        int c = (lane & 3) * 2;
        cf0 = __cosf(fTh[c]); cf1 = __cosf(fTh[c + 1]);
    }
    float ps[8][2];
    if constexpr (PROD == 2) {
#pragma unroll
        for (int ni = 0; ni < 8; ni++) { ps[ni][0] = 0.f; ps[ni][1] = 0.f; }
    }

#pragma unroll
    for (int mi = 0; mi < 4; mi++) {
        int rl = r0l + mi * 16;
        float2 m0 = mr[rl], m1 = mr[rl + 8];
#pragma unroll
        for (int ni = 0; ni < 8; ni++) {
            int col = mcol + ni * 8;
            float gx = lnG[col], gy = lnG[col + 1];
            float bx = lnB[col], by = lnB[col + 1];
            float o0 = (acc[mi][ni][0] - m0.x) * m0.y * gx + bx;
            float o1 = (acc[mi][ni][1] - m0.x) * m0.y * gy + by;
            float o2 = (acc[mi][ni][2] - m1.x) * m1.y * gx + bx;
            float o3 = (acc[mi][ni][3] - m1.x) * m1.y * gy + by;
            if constexpr (PROD != 2) {
                xr[rl * 128 + (col >> 1)] =
                    __halves2half2(__float2half_rn(o0), __float2half_rn(o1));
                xr[(rl + 8) * 128 + (col >> 1)] =
                    __halves2half2(__float2half_rn(o2), __float2half_rn(o3));
            }
            if constexpr (PROD == 0) {
                if (wn == 0 && ni == 0) {
                    int c = (lane & 3) * 2;
                    qsh[rl * 8 + c]           = __cosf(o0) * cf0;
                    qsh[rl * 8 + c + 1]       = __cosf(o1) * cf1;
                    qsh[(rl + 8) * 8 + c]     = __cosf(o2) * cf0;
                    qsh[(rl + 8) * 8 + c + 1] = __cosf(o3) * cf1;
                }
            }
            if constexpr (PROD == 2) {
                ps[ni][0] += o0 + o2;
                ps[ni][1] += o1 + o3;
            }
        }
    }

    if constexpr (PROD == 2) {
#pragma unroll
        for (int ni = 0; ni < 8; ni++)
#pragma unroll
            for (int o = 4; o <= 16; o <<= 1) {
                ps[ni][0] += __shfl_xor_sync(0xffffffffu, ps[ni][0], o);
                ps[ni][1] += __shfl_xor_sync(0xffffffffu, ps[ni][1], o);
            }
        if (lane < 4) {
#pragma unroll
            for (int ni = 0; ni < 8; ni++) {
                g_pp[blockIdx.x * 256 + mcol + ni * 8]     = ps[ni][0];
                g_pp[blockIdx.x * 256 + mcol + ni * 8 + 1] = ps[ni][1];
            }
        }
    }
}

// ---------------- whole network, activations CTA-resident in smem ------------
__global__ void __launch_bounds__(128, 2)
k_net(const int* __restrict__ tokens, const float* __restrict__ emb,
      const float* __restrict__ attn_theta,
      const float* __restrict__ combine_b,
      const float* __restrict__ ffn_theta,
      const float* __restrict__ lin1_w, const float* __restrict__ lin1_b,
      const float* __restrict__ lin2_b,
      const float* __restrict__ ln1_g, const float* __restrict__ ln1_b,
      const float* __restrict__ ln2_g, const float* __restrict__ ln2_b) {
    extern __shared__ __align__(16) char smem[];
    uint32_t sb = s2u(smem);
    int tid = threadIdx.x;
    size_t bm = (size_t)blockIdx.x * 64;

    float* w1s = (float*)(smem + W1S_O);
    float* b1s = (float*)(smem + B1S_O);
    float* qsh = (float*)(smem + QSH_O);

    // ---- embed prologue: rows bm..bm+63 -> xres (fp16, smem) ----
    {
        __half2* xr = (__half2*)(smem + XRES_O);
#pragma unroll
        for (int i = 0; i < 32; i++) {
            int idx = tid + i * 128;
            int r   = idx >> 6;
            int c   = (idx & 63) * 4;
            size_t row = bm + r;
            int s = (int)(row & (S_ - 1));
            int t = tokens[row];
            float4 ev = *(const float4*)(emb + (size_t)t * E_ + c);
            float xs[4];
#pragma unroll
            for (int j = 0; j < 4; j++) {
                int e = c + j;
                float freq = __expf(-(float)(e & ~1) * (9.210340371976184f / (float)E_));
                float ang  = (float)s * freq;
                float pe   = (e & 1) ? __cosf(ang) : __sinf(ang);
                xs[j] = ((const float*)&ev)[j] + pe;
            }
            xr[r * 128 + (c >> 1)] =
                __halves2half2(__float2half_rn(xs[0]), __float2half_rn(xs[1]));
            xr[r * 128 + (c >> 1) + 1] =
                __halves2half2(__float2half_rn(xs[2]), __float2half_rn(xs[3]));
        }
    }
    __syncthreads();

    float acc[4][8][4];
#pragma unroll
    for (int l = 0; l < L_; l++) {
        // stage W1/b1 for this layer (first use is ffn comp_h, after barriers)
#pragma unroll
        for (int i = 0; i < 32; i++)
            w1s[tid + i * 128] = lin1_w[(size_t)l * NQ_ * FFN_ + tid + i * 128];
#pragma unroll
        for (int i = 0; i < 4; i++)
            b1s[tid + i * 128] = lin1_b[l * FFN_ + tid + i * 128];

        // attn GEMM (K=256, A = cos(xres+theta) computed in-CTA)
#pragma unroll
        for (int i = 0; i < 4; i++)
#pragma unroll
            for (int j = 0; j < 8; j++)
#pragma unroll
                for (int c = 0; c < 4; c++) acc[i][j][c] = 0.f;
        run_gemm<256, 0>(acc, smem, sb, attn_theta + l * 64,
                         g_wh + (size_t)l * 131072, nullptr, nullptr, nullptr);
        epilogue<0>(acc, smem, combine_b + l * E_,
                    ln1_g + l * E_, ln1_b + l * E_, ffn_theta + l * NQ_);
        __syncthreads();   // qsh + xres ready

        // ffn GEMM (K=512, A = relu(q@W1+b1) computed in-CTA)
#pragma unroll
        for (int i = 0; i < 4; i++)
#pragma unroll
            for (int j = 0; j < 8; j++)
#pragma unroll
                for (int c = 0; c < 4; c++) acc[i][j][c] = 0.f;
        run_gemm<512, 1>(acc, smem, sb, nullptr,
                         g_wh + (size_t)(2 + l) * 131072, qsh, w1s, b1s);
        if (l == 0) {
            epilogue<1>(acc, smem, lin2_b, ln2_g, ln2_b, nullptr);
            __syncthreads();   // xres ready for layer-1 comp_a
        } else {
            epilogue<2>(acc, smem, lin2_b + E_, ln2_g + E_, ln2_b + E_, nullptr);
        }
    }
}

// ---------------- classifier -------------------------------------------------
__global__ void k_cls(const float* __restrict__ w, const float* __restrict__ cb,
                      float* __restrict__ out) {
    __shared__ float sh[16];
    int b = blockIdx.x, e = threadIdx.x;
    float p = 0.f;
#pragma unroll 8
    for (int j = 0; j < 32; j++) p += g_pp[(b * 32 + j) * E_ + e];
    p *= (1.0f / (float)S_);
    float s0 = p * w[e * 2], s1 = p * w[e * 2 + 1];
    for (int o = 16; o > 0; o >>= 1) {
        s0 += __shfl_xor_sync(0xffffffffu, s0, o);
        s1 += __shfl_xor_sync(0xffffffffu, s1, o);
    }
    int wi = e >> 5;
    if ((e & 31) == 0) { sh[wi * 2] = s0; sh[wi * 2 + 1] = s1; }
    __syncthreads();
    if (e == 0) {
        float t0 = 0, t1 = 0;
#pragma unroll
        for (int j = 0; j < 8; j++) { t0 += sh[j * 2]; t1 += sh[j * 2 + 1]; }
        out[b * 2]     = t0 + cb[0];
        out[b * 2 + 1] = t1 + cb[1];
    }
}

// ---------------- host launcher ----------------------------------------------
extern "C" void kernel_launch(void* const* d_in, const int* in_sizes, int n_in,
                              void* d_out, int out_size) {
    const int*   tokens     = (const int*)d_in[0];
    const float* embed      = (const float*)d_in[1];
    const float* attn_theta = (const float*)d_in[2];
    const float* combine_w  = (const float*)d_in[3];
    const float* combine_b  = (const float*)d_in[4];
    const float* ffn_theta  = (const float*)d_in[5];
    const float* lin1_w     = (const float*)d_in[6];
    const float* lin1_b     = (const float*)d_in[7];
    const float* lin2_w     = (const float*)d_in[8];
    const float* lin2_b     = (const float*)d_in[9];
    const float* ln1_g      = (const float*)d_in[10];
    const float* ln1_b      = (const float*)d_in[11];
    const float* ln2_g      = (const float*)d_in[12];
    const float* ln2_b      = (const float*)d_in[13];
    const float* cls_w      = (const float*)d_in[14];
    const float* cls_b      = (const float*)d_in[15];
    float* out = (float*)d_out;

    cudaFuncSetAttribute(k_net, cudaFuncAttributeMaxDynamicSharedMemorySize, SME_T);

    k_convw<<<dim3(256, 4), 256>>>(combine_w, lin2_w);
    k_net<<<M_ / 64, 128, SME_T>>>(tokens, embed, attn_theta, combine_b,
                                   ffn_theta, lin1_w, lin1_b, lin2_b,
                                   ln1_g, ln1_b, ln2_g, ln2_b);
    k_cls<<<B_, 256>>>(cls_w, cls_b, out);
}